// round 1
// baseline (speedup 1.0000x reference)
#include <cuda_runtime.h>
#include <cuda_bf16.h>
#include <math.h>

// ---------------------------------------------------------------------------
// Problem constants
// ---------------------------------------------------------------------------
#define TOK   50176      // 2*8*56*56
#define CDIM  128
#define CH    512
#define NWIN  512        // 2 * 4*8*8
#define NTOK  98         // 2*7*7
#define NH    4
#define HD    32
#define QKVN  384

// ---------------------------------------------------------------------------
// Scratch (device globals: allocation-free, graph-capture safe)
// ---------------------------------------------------------------------------
__device__ float g_xw  [(size_t)TOK * CDIM];   // LN1 out (window order) / LN2 out (spatial)
__device__ float g_qkv [(size_t)TOK * QKVN];   // qkv, window order
__device__ float g_attn[(size_t)TOK * CDIM];   // attention out, window order
__device__ float g_x2  [(size_t)TOK * CDIM];   // x + proj (spatial)
__device__ float g_h   [(size_t)TOK * CH];     // fc1 output
__device__ float g_bias[NH * NTOK * NTOK];     // gathered attention bias

// ---------------------------------------------------------------------------
// index helpers
// ---------------------------------------------------------------------------
__device__ __forceinline__ long win_to_spatial(long row) {
    int w = (int)(row / NTOK);
    int n = (int)(row % NTOK);
    int b   = w >> 8;           // 256 windows per batch
    int rem = w & 255;
    int wdi = rem >> 6, whi = (rem >> 3) & 7, wwi = rem & 7;
    int zd = n / 49; int r2 = n % 49; int zh = r2 / 7, zw = r2 % 7;
    int d  = wdi * 2 + zd;
    int hh = whi * 7 + zh;
    int xx = wwi * 7 + zw;
    return (((long)(b * 8 + d) * 56) + hh) * 56 + xx;
}

__device__ __forceinline__ long spatial_to_win(long t) {
    int b  = (int)(t / 25088);
    int r  = (int)(t % 25088);
    int d  = r / 3136; r %= 3136;
    int hh = r / 56;
    int xx = r % 56;
    int widx = ((b * 4 + (d >> 1)) * 8 + hh / 7) * 8 + xx / 7;
    int n    = ((d & 1) * 7 + hh % 7) * 7 + xx % 7;
    return (long)widx * NTOK + n;
}

// ---------------------------------------------------------------------------
// bias gather: g_bias[h][n][m] = bias_table[rel_index[n][m]][h]
// ---------------------------------------------------------------------------
__global__ void bias_gather_kernel(const float* __restrict__ bias_table,
                                   const int* __restrict__ rel_index) {
    int m = threadIdx.x;       // 0..97
    int n = blockIdx.x;        // 0..97
    int h = blockIdx.y;        // 0..3
    int idx = rel_index[n * NTOK + m];
    g_bias[(h * NTOK + n) * NTOK + m] = bias_table[idx * NH + h];
}

// ---------------------------------------------------------------------------
// LayerNorm over C=128, one token per block (128 threads).
// PERMUTE=true: write window-partitioned order (for LN1).
// ---------------------------------------------------------------------------
template<bool PERMUTE>
__global__ __launch_bounds__(128)
void ln_kernel(const float* __restrict__ in,
               const float* __restrict__ gam,
               const float* __restrict__ bet,
               float* __restrict__ out) {
    long t = blockIdx.x;
    int  c = threadIdx.x;
    float v = in[t * CDIM + c];
    float s = v, sq = v * v;
    #pragma unroll
    for (int o = 16; o; o >>= 1) {
        s  += __shfl_xor_sync(0xffffffffu, s,  o);
        sq += __shfl_xor_sync(0xffffffffu, sq, o);
    }
    __shared__ float ss[4], ssq[4];
    int wid = c >> 5, lane = c & 31;
    if (lane == 0) { ss[wid] = s; ssq[wid] = sq; }
    __syncthreads();
    s  = ss[0] + ss[1] + ss[2] + ss[3];
    sq = ssq[0] + ssq[1] + ssq[2] + ssq[3];
    float mean = s * (1.0f / CDIM);
    float var  = sq * (1.0f / CDIM) - mean * mean;
    float y = (v - mean) * rsqrtf(var + 1e-5f) * gam[c] + bet[c];
    long orow = PERMUTE ? spatial_to_win(t) : t;
    out[orow * CDIM + c] = y;
}

// ---------------------------------------------------------------------------
// Tiled fp32 GEMM: C[M,N] = A[M,K] @ W[N,K]^T (+ epilogue)
// BM=128 BN=64 BK=16, 256 threads, 8x4 per thread.
// MODE 0: qkv   -> c += bias; scale q-part by 1/sqrt(32); C row-major [M,384]
// MODE 1: proj  -> c += bias; spatial permute row; += resid(x); write g_x2
// MODE 2: fc1   -> c += bias; exact-erf GELU; C [M,512]
// MODE 3: fc2   -> c += bias; += resid(g_x2); write d_out
// ---------------------------------------------------------------------------
template<int MODE>
__global__ __launch_bounds__(256)
void gemm_kernel(const float* __restrict__ A,
                 const float* __restrict__ Wt,
                 const float* __restrict__ bias,
                 const float* __restrict__ resid,
                 float* __restrict__ C,
                 int N, int K) {
    const int BM = 128, BN = 64, BK = 16;
    __shared__ float As[BK][BM];
    __shared__ float Ws[BK][BN];

    int tid = threadIdx.x;
    int tx  = tid & 15;   // column group -> 4 cols
    int ty  = tid >> 4;   // row group    -> 8 rows
    long rowBase = (long)blockIdx.y * BM;
    int  colBase = blockIdx.x * BN;

    float acc[8][4];
    #pragma unroll
    for (int i = 0; i < 8; i++)
        #pragma unroll
        for (int j = 0; j < 4; j++) acc[i][j] = 0.f;

    for (int k0 = 0; k0 < K; k0 += BK) {
        #pragma unroll
        for (int r = 0; r < 2; r++) {              // A tile: 512 float4
            int idx  = tid + r * 256;
            int arow = idx >> 2;
            int akq  = (idx & 3) * 4;
            const float4 a = *(const float4*)(A + (rowBase + arow) * K + k0 + akq);
            As[akq + 0][arow] = a.x; As[akq + 1][arow] = a.y;
            As[akq + 2][arow] = a.z; As[akq + 3][arow] = a.w;
        }
        {                                           // W tile: 256 float4
            int wrow = tid >> 2;
            int wkq  = (tid & 3) * 4;
            const float4 w = *(const float4*)(Wt + (long)(colBase + wrow) * K + k0 + wkq);
            Ws[wkq + 0][wrow] = w.x; Ws[wkq + 1][wrow] = w.y;
            Ws[wkq + 2][wrow] = w.z; Ws[wkq + 3][wrow] = w.w;
        }
        __syncthreads();
        #pragma unroll
        for (int kk = 0; kk < BK; kk++) {
            float4 a0 = *(const float4*)&As[kk][ty * 8];
            float4 a1 = *(const float4*)&As[kk][ty * 8 + 4];
            float4 w0 = *(const float4*)&Ws[kk][tx * 4];
            float av[8] = {a0.x, a0.y, a0.z, a0.w, a1.x, a1.y, a1.z, a1.w};
            float wv[4] = {w0.x, w0.y, w0.z, w0.w};
            #pragma unroll
            for (int i = 0; i < 8; i++)
                #pragma unroll
                for (int j = 0; j < 4; j++)
                    acc[i][j] += av[i] * wv[j];
        }
        __syncthreads();
    }

    int col0 = colBase + tx * 4;
    #pragma unroll
    for (int i = 0; i < 8; i++) {
        long row = rowBase + ty * 8 + i;
        float4 o;
        float* po = (float*)&o;
        #pragma unroll
        for (int j = 0; j < 4; j++) {
            float c = acc[i][j] + bias[col0 + j];
            if (MODE == 0) { if (col0 + j < CDIM) c *= 0.17677669529663687f; }
            if (MODE == 2) { c = 0.5f * c * (1.0f + erff(c * 0.70710678118654752f)); }
            po[j] = c;
        }
        if (MODE == 1) {
            long s = win_to_spatial(row);
            float4 r = *(const float4*)(resid + s * CDIM + col0);
            o.x += r.x; o.y += r.y; o.z += r.z; o.w += r.w;
            *(float4*)(C + s * CDIM + col0) = o;
        } else if (MODE == 3) {
            float4 r = *(const float4*)(resid + row * CDIM + col0);
            o.x += r.x; o.y += r.y; o.z += r.z; o.w += r.w;
            *(float4*)(C + row * CDIM + col0) = o;
        } else {
            *(float4*)(C + row * (long)N + col0) = o;
        }
    }
}

// ---------------------------------------------------------------------------
// Window attention: one block per (window, head). 128 threads.
// q in registers, k/v in smem, 98x98 scores in padded smem.
// ---------------------------------------------------------------------------
__global__ __launch_bounds__(128)
void attn_kernel() {
    extern __shared__ float sm[];
    float* k_s = sm;                       // 98*32
    float* v_s = sm + NTOK * HD;           // 98*32
    float* p_s = sm + 2 * NTOK * HD;       // 98*99 (pad for bank-free col walk)
    const int PST = NTOK + 1;              // 99

    int w = blockIdx.x;
    int h = blockIdx.y;
    int tid = threadIdx.x;

    const float* base = g_qkv + (size_t)w * NTOK * QKVN + h * HD;

    // cooperative load of K and V tiles (float4, coalesced)
    for (int i = tid; i < NTOK * (HD / 4); i += 128) {
        int m  = i >> 3;
        int dq = (i & 7) * 4;
        *(float4*)&k_s[m * HD + dq] = *(const float4*)(base + m * QKVN + CDIM     + dq);
        *(float4*)&v_s[m * HD + dq] = *(const float4*)(base + m * QKVN + 2 * CDIM + dq);
    }
    __syncthreads();

    if (tid < NTOK) {
        float q[HD];
        const float* qp = base + tid * QKVN;
        #pragma unroll
        for (int d = 0; d < HD; d++) q[d] = qp[d];   // already scaled by 1/sqrt(hd)

        const float* brow = g_bias + (h * NTOK + tid) * NTOK;
        float mx = -1e30f;
        for (int m = 0; m < NTOK; m++) {
            float s = 0.f;
            #pragma unroll
            for (int d = 0; d < HD; d++) s += q[d] * k_s[m * HD + d];
            s += brow[m];
            p_s[tid * PST + m] = s;
            mx = fmaxf(mx, s);
        }
        float sum = 0.f;
        for (int m = 0; m < NTOK; m++) {
            float e = __expf(p_s[tid * PST + m] - mx);
            p_s[tid * PST + m] = e;
            sum += e;
        }
        float inv = 1.0f / sum;

        float accv[HD];
        #pragma unroll
        for (int d = 0; d < HD; d++) accv[d] = 0.f;
        for (int m = 0; m < NTOK; m++) {
            float p = p_s[tid * PST + m];
            #pragma unroll
            for (int d = 0; d < HD; d++) accv[d] += p * v_s[m * HD + d];
        }
        float* op = g_attn + ((size_t)w * NTOK + tid) * CDIM + h * HD;
        #pragma unroll
        for (int dq = 0; dq < HD; dq += 4) {
            float4 o = make_float4(accv[dq] * inv, accv[dq + 1] * inv,
                                   accv[dq + 2] * inv, accv[dq + 3] * inv);
            *(float4*)(op + dq) = o;
        }
    }
}

// ---------------------------------------------------------------------------
// launcher
// ---------------------------------------------------------------------------
extern "C" void kernel_launch(void* const* d_in, const int* in_sizes, int n_in,
                              void* d_out, int out_size) {
    const float* x          = (const float*)d_in[0];
    const float* norm1_w    = (const float*)d_in[1];
    const float* norm1_b    = (const float*)d_in[2];
    const float* qkv_w      = (const float*)d_in[3];
    const float* qkv_b      = (const float*)d_in[4];
    const float* bias_table = (const float*)d_in[5];
    const float* proj_w     = (const float*)d_in[6];
    const float* proj_b     = (const float*)d_in[7];
    const float* norm2_w    = (const float*)d_in[8];
    const float* norm2_b    = (const float*)d_in[9];
    const float* fc1_w      = (const float*)d_in[10];
    const float* fc1_b      = (const float*)d_in[11];
    const float* fc2_w      = (const float*)d_in[12];
    const float* fc2_b      = (const float*)d_in[13];
    const int*   rel_index  = (const int*)d_in[14];
    float* out = (float*)d_out;

    // resolve scratch symbol addresses
    float *p_xw, *p_qkv, *p_attn, *p_x2, *p_h;
    cudaGetSymbolAddress((void**)&p_xw,   g_xw);
    cudaGetSymbolAddress((void**)&p_qkv,  g_qkv);
    cudaGetSymbolAddress((void**)&p_attn, g_attn);
    cudaGetSymbolAddress((void**)&p_x2,   g_x2);
    cudaGetSymbolAddress((void**)&p_h,    g_h);

    // attention needs 62.4 KB dynamic smem
    const int ATTN_SMEM = (2 * NTOK * HD + NTOK * (NTOK + 1)) * (int)sizeof(float);
    cudaFuncSetAttribute(attn_kernel, cudaFuncAttributeMaxDynamicSharedMemorySize, ATTN_SMEM);

    // 0) gather relative position bias
    bias_gather_kernel<<<dim3(NTOK, NH), NTOK>>>(bias_table, rel_index);

    // 1) LN1 + window partition
    ln_kernel<true><<<TOK, 128>>>(x, norm1_w, norm1_b, p_xw);

    // 2) QKV gemm (+ q scale)
    gemm_kernel<0><<<dim3(QKVN / 64, TOK / 128), 256>>>(p_xw, qkv_w, qkv_b, nullptr, p_qkv, QKVN, CDIM);

    // 3) window attention
    attn_kernel<<<dim3(NWIN, NH), 128, ATTN_SMEM>>>();

    // 4) proj gemm + window reverse + residual(x) -> g_x2 (spatial)
    gemm_kernel<1><<<dim3(CDIM / 64, TOK / 128), 256>>>(p_attn, proj_w, proj_b, x, p_x2, CDIM, CDIM);

    // 5) LN2 (spatial -> spatial)
    ln_kernel<false><<<TOK, 128>>>(p_x2, norm2_w, norm2_b, p_xw);

    // 6) fc1 + exact GELU
    gemm_kernel<2><<<dim3(CH / 64, TOK / 128), 256>>>(p_xw, fc1_w, fc1_b, nullptr, p_h, CH, CDIM);

    // 7) fc2 + residual(g_x2) -> d_out
    gemm_kernel<3><<<dim3(CDIM / 64, TOK / 128), 256>>>(p_h, fc2_w, fc2_b, p_x2, out, CDIM, CH);

    (void)in_sizes; (void)n_in; (void)out_size;
}

// round 2
// speedup vs baseline: 1.9422x; 1.9422x over previous
#include <cuda_runtime.h>
#include <cuda_bf16.h>
#include <math.h>
#include <stdint.h>

// ---------------------------------------------------------------------------
// Problem constants
// ---------------------------------------------------------------------------
#define TOK   50176      // 2*8*56*56
#define CDIM  128
#define CH    512
#define NWIN  512        // 2 * 4*8*8
#define NTOK  98         // 2*7*7
#define NH    4
#define HD    32
#define QKVN  384

// ---------------------------------------------------------------------------
// Scratch (device globals: allocation-free, graph-capture safe)
// ---------------------------------------------------------------------------
__device__ float g_xw  [(size_t)TOK * CDIM];   // LN1 out (window order) / LN2 out (spatial)
__device__ float g_qkv [(size_t)TOK * QKVN];   // qkv, window order
__device__ float g_attn[(size_t)TOK * CDIM];   // attention out, window order
__device__ float g_x2  [(size_t)TOK * CDIM];   // x + proj (spatial)
__device__ float g_h   [(size_t)TOK * CH];     // fc1 output
__device__ float g_bias[NH * NTOK * NTOK];     // gathered attention bias

// ---------------------------------------------------------------------------
// index helpers
// ---------------------------------------------------------------------------
__device__ __forceinline__ long win_to_spatial(long row) {
    int w = (int)(row / NTOK);
    int n = (int)(row % NTOK);
    int b   = w >> 8;           // 256 windows per batch
    int rem = w & 255;
    int wdi = rem >> 6, whi = (rem >> 3) & 7, wwi = rem & 7;
    int zd = n / 49; int r2 = n % 49; int zh = r2 / 7, zw = r2 % 7;
    int d  = wdi * 2 + zd;
    int hh = whi * 7 + zh;
    int xx = wwi * 7 + zw;
    return (((long)(b * 8 + d) * 56) + hh) * 56 + xx;
}

__device__ __forceinline__ long spatial_to_win(long t) {
    int b  = (int)(t / 25088);
    int r  = (int)(t % 25088);
    int d  = r / 3136; r %= 3136;
    int hh = r / 56;
    int xx = r % 56;
    int widx = ((b * 4 + (d >> 1)) * 8 + hh / 7) * 8 + xx / 7;
    int n    = ((d & 1) * 7 + hh % 7) * 7 + xx % 7;
    return (long)widx * NTOK + n;
}

// ---------------------------------------------------------------------------
// bias gather: g_bias[h][n][m] = bias_table[rel_index[n][m]][h]
// ---------------------------------------------------------------------------
__global__ void bias_gather_kernel(const float* __restrict__ bias_table,
                                   const int* __restrict__ rel_index) {
    int m = threadIdx.x;       // 0..97
    int n = blockIdx.x;        // 0..97
    int h = blockIdx.y;        // 0..3
    int idx = rel_index[n * NTOK + m];
    g_bias[(h * NTOK + n) * NTOK + m] = bias_table[idx * NH + h];
}

// ---------------------------------------------------------------------------
// LayerNorm over C=128: one warp per token, float4 per lane. 256 thr/block.
// PERMUTE=true: write window-partitioned order (for LN1).
// ---------------------------------------------------------------------------
template<bool PERMUTE>
__global__ __launch_bounds__(256)
void ln_kernel(const float* __restrict__ in,
               const float* __restrict__ gam,
               const float* __restrict__ bet,
               float* __restrict__ out) {
    int warp = threadIdx.x >> 5;
    int lane = threadIdx.x & 31;
    long t = (long)blockIdx.x * 8 + warp;
    const float4 v = *(const float4*)(in + t * CDIM + lane * 4);
    float s  = v.x + v.y + v.z + v.w;
    float sq = v.x * v.x + v.y * v.y + v.z * v.z + v.w * v.w;
    #pragma unroll
    for (int o = 16; o; o >>= 1) {
        s  += __shfl_xor_sync(0xffffffffu, s,  o);
        sq += __shfl_xor_sync(0xffffffffu, sq, o);
    }
    float mean = s * (1.0f / CDIM);
    float var  = sq * (1.0f / CDIM) - mean * mean;
    float rstd = rsqrtf(var + 1e-5f);
    const float4 g = *(const float4*)(gam + lane * 4);
    const float4 b = *(const float4*)(bet + lane * 4);
    float4 y;
    y.x = (v.x - mean) * rstd * g.x + b.x;
    y.y = (v.y - mean) * rstd * g.y + b.y;
    y.z = (v.z - mean) * rstd * g.z + b.z;
    y.w = (v.w - mean) * rstd * g.w + b.w;
    long orow = PERMUTE ? spatial_to_win(t) : t;
    *(float4*)(out + orow * CDIM + lane * 4) = y;
}

// ---------------------------------------------------------------------------
// tf32 mma.sync m16n8k8 (row.col), fp32 accumulate
// ---------------------------------------------------------------------------
__device__ __forceinline__ void mma_tf32(float c[4], const uint32_t a[4], const uint32_t b[2]) {
    asm volatile(
        "mma.sync.aligned.m16n8k8.row.col.f32.tf32.tf32.f32 "
        "{%0,%1,%2,%3}, {%4,%5,%6,%7}, {%8,%9}, {%0,%1,%2,%3};\n"
        : "+f"(c[0]), "+f"(c[1]), "+f"(c[2]), "+f"(c[3])
        : "r"(a[0]), "r"(a[1]), "r"(a[2]), "r"(a[3]), "r"(b[0]), "r"(b[1]));
}

// ---------------------------------------------------------------------------
// TF32 tensor-core GEMM: C[M,N] = A[M,K] @ W[N,K]^T (+ epilogue)
// BM=128 BN=64 BK=32, 256 threads (8 warps as 4x2), warp tile 32x32.
// MODE 0: qkv   -> +bias; scale q-part by 1/sqrt(32); C row-major [M,384]
// MODE 1: proj  -> +bias; spatial permute row; += resid(x); write g_x2
// MODE 2: fc1   -> +bias; exact-erf GELU; C [M,512]
// MODE 3: fc2   -> +bias; += resid(g_x2); write d_out
// ---------------------------------------------------------------------------
#define APAD 36
template<int MODE>
__global__ __launch_bounds__(256)
void gemm_kernel(const float* __restrict__ A,
                 const float* __restrict__ Wt,
                 const float* __restrict__ bias,
                 const float* __restrict__ resid,
                 float* __restrict__ C,
                 int N, int K) {
    __shared__ float As[128][APAD];
    __shared__ float Ws[64][APAD];

    const int tid  = threadIdx.x;
    const int lane = tid & 31;
    const int warp = tid >> 5;
    const int warpM = warp >> 1;        // 0..3
    const int warpN = warp & 1;         // 0..1
    const int gid = lane >> 2;          // 0..7
    const int tig = lane & 3;           // 0..3

    const long rowBase = (long)blockIdx.y * 128;
    const int  colBase = blockIdx.x * 64;

    float cc[2][4][4];
    #pragma unroll
    for (int mi = 0; mi < 2; mi++)
        #pragma unroll
        for (int ni = 0; ni < 4; ni++)
            #pragma unroll
            for (int e = 0; e < 4; e++) cc[mi][ni][e] = 0.f;

    const uint32_t* Asu = (const uint32_t*)&As[0][0];
    const uint32_t* Wsu = (const uint32_t*)&Ws[0][0];

    for (int k0 = 0; k0 < K; k0 += 32) {
        // A tile: 128 rows x 32 k = 1024 float4
        #pragma unroll
        for (int r = 0; r < 4; r++) {
            int idx = tid + r * 256;
            int m   = idx >> 3;
            int kq  = (idx & 7) * 4;
            *(float4*)&As[m][kq] = *(const float4*)(A + (rowBase + m) * K + k0 + kq);
        }
        // W tile: 64 rows x 32 k = 512 float4
        #pragma unroll
        for (int r = 0; r < 2; r++) {
            int idx = tid + r * 256;
            int n   = idx >> 3;
            int kq  = (idx & 7) * 4;
            *(float4*)&Ws[n][kq] = *(const float4*)(Wt + (long)(colBase + n) * K + k0 + kq);
        }
        __syncthreads();

        #pragma unroll
        for (int ks = 0; ks < 4; ks++) {
            const int kk = ks * 8;
            uint32_t af[2][4];
            uint32_t bf[4][2];
            #pragma unroll
            for (int mi = 0; mi < 2; mi++) {
                int r = warpM * 32 + mi * 16 + gid;
                af[mi][0] = Asu[(r    ) * APAD + kk + tig];
                af[mi][1] = Asu[(r + 8) * APAD + kk + tig];
                af[mi][2] = Asu[(r    ) * APAD + kk + tig + 4];
                af[mi][3] = Asu[(r + 8) * APAD + kk + tig + 4];
            }
            #pragma unroll
            for (int ni = 0; ni < 4; ni++) {
                int n = warpN * 32 + ni * 8 + gid;
                bf[ni][0] = Wsu[n * APAD + kk + tig];
                bf[ni][1] = Wsu[n * APAD + kk + tig + 4];
            }
            #pragma unroll
            for (int mi = 0; mi < 2; mi++)
                #pragma unroll
                for (int ni = 0; ni < 4; ni++)
                    mma_tf32(cc[mi][ni], af[mi], bf[ni]);
        }
        __syncthreads();
    }

    // epilogue
    #pragma unroll
    for (int mi = 0; mi < 2; mi++) {
        #pragma unroll
        for (int half = 0; half < 2; half++) {
            long row  = rowBase + warpM * 32 + mi * 16 + gid + half * 8;
            long orow = (MODE == 1) ? win_to_spatial(row) : row;
            #pragma unroll
            for (int ni = 0; ni < 4; ni++) {
                int col = colBase + warpN * 32 + ni * 8 + 2 * tig;
                float v0 = cc[mi][ni][half * 2 + 0] + bias[col];
                float v1 = cc[mi][ni][half * 2 + 1] + bias[col + 1];
                if (MODE == 0) {
                    if (col < CDIM) { v0 *= 0.17677669529663687f; v1 *= 0.17677669529663687f; }
                }
                if (MODE == 2) {
                    v0 = 0.5f * v0 * (1.0f + erff(v0 * 0.70710678118654752f));
                    v1 = 0.5f * v1 * (1.0f + erff(v1 * 0.70710678118654752f));
                }
                if (MODE == 1 || MODE == 3) {
                    const float2 r = *(const float2*)(resid + orow * CDIM + col);
                    v0 += r.x; v1 += r.y;
                    float2 o = make_float2(v0, v1);
                    *(float2*)(C + orow * CDIM + col) = o;
                } else {
                    float2 o = make_float2(v0, v1);
                    *(float2*)(C + row * (long)N + col) = o;
                }
            }
        }
    }
}

// ---------------------------------------------------------------------------
// Window attention: one block per (window, head). 128 threads, 98 active.
// Single-pass fused softmax (scores are tiny -> no max subtraction needed;
// softmax is shift-invariant so result is mathematically identical).
// q in registers, k/v in smem as float4 broadcast loads.
// ---------------------------------------------------------------------------
__global__ __launch_bounds__(128)
void attn_kernel() {
    __shared__ float k_s[NTOK * HD];
    __shared__ float v_s[NTOK * HD];

    const int w = blockIdx.x;
    const int h = blockIdx.y;
    const int tid = threadIdx.x;

    const float* base = g_qkv + (size_t)w * NTOK * QKVN + h * HD;

    // cooperative load of K and V tiles (float4, coalesced)
    for (int i = tid; i < NTOK * (HD / 4); i += 128) {
        int m  = i >> 3;
        int dq = (i & 7) * 4;
        *(float4*)&k_s[m * HD + dq] = *(const float4*)(base + m * QKVN + CDIM     + dq);
        *(float4*)&v_s[m * HD + dq] = *(const float4*)(base + m * QKVN + 2 * CDIM + dq);
    }
    __syncthreads();

    if (tid < NTOK) {
        float4 q[8];
        const float* qp = base + tid * QKVN;   // already scaled by 1/sqrt(hd)
        #pragma unroll
        for (int j = 0; j < 8; j++) q[j] = *(const float4*)(qp + j * 4);

        const float* brow = g_bias + (h * NTOK + tid) * NTOK;

        float sum = 0.f;
        float acc[HD];
        #pragma unroll
        for (int d = 0; d < HD; d++) acc[d] = 0.f;

        #pragma unroll 2
        for (int m = 0; m < NTOK; m++) {
            const float4* kp = (const float4*)&k_s[m * HD];
            float s0 = 0.f, s1 = 0.f, s2 = 0.f, s3 = 0.f;
            #pragma unroll
            for (int j = 0; j < 8; j++) {
                float4 kv = kp[j];
                s0 += q[j].x * kv.x;
                s1 += q[j].y * kv.y;
                s2 += q[j].z * kv.z;
                s3 += q[j].w * kv.w;
            }
            float s = brow[m] + ((s0 + s1) + (s2 + s3));
            float e = __expf(s);
            sum += e;
            const float4* vp = (const float4*)&v_s[m * HD];
            #pragma unroll
            for (int j = 0; j < 8; j++) {
                float4 vv = vp[j];
                acc[4 * j + 0] += e * vv.x;
                acc[4 * j + 1] += e * vv.y;
                acc[4 * j + 2] += e * vv.z;
                acc[4 * j + 3] += e * vv.w;
            }
        }
        float inv = 1.0f / sum;
        float* op = g_attn + ((size_t)w * NTOK + tid) * CDIM + h * HD;
        #pragma unroll
        for (int j = 0; j < 8; j++) {
            float4 o = make_float4(acc[4 * j] * inv, acc[4 * j + 1] * inv,
                                   acc[4 * j + 2] * inv, acc[4 * j + 3] * inv);
            *(float4*)(op + 4 * j) = o;
        }
    }
}

// ---------------------------------------------------------------------------
// launcher
// ---------------------------------------------------------------------------
extern "C" void kernel_launch(void* const* d_in, const int* in_sizes, int n_in,
                              void* d_out, int out_size) {
    const float* x          = (const float*)d_in[0];
    const float* norm1_w    = (const float*)d_in[1];
    const float* norm1_b    = (const float*)d_in[2];
    const float* qkv_w      = (const float*)d_in[3];
    const float* qkv_b      = (const float*)d_in[4];
    const float* bias_table = (const float*)d_in[5];
    const float* proj_w     = (const float*)d_in[6];
    const float* proj_b     = (const float*)d_in[7];
    const float* norm2_w    = (const float*)d_in[8];
    const float* norm2_b    = (const float*)d_in[9];
    const float* fc1_w      = (const float*)d_in[10];
    const float* fc1_b      = (const float*)d_in[11];
    const float* fc2_w      = (const float*)d_in[12];
    const float* fc2_b      = (const float*)d_in[13];
    const int*   rel_index  = (const int*)d_in[14];
    float* out = (float*)d_out;

    float *p_xw, *p_qkv, *p_attn, *p_x2, *p_h;
    cudaGetSymbolAddress((void**)&p_xw,   g_xw);
    cudaGetSymbolAddress((void**)&p_qkv,  g_qkv);
    cudaGetSymbolAddress((void**)&p_attn, g_attn);
    cudaGetSymbolAddress((void**)&p_x2,   g_x2);
    cudaGetSymbolAddress((void**)&p_h,    g_h);

    // 0) gather relative position bias
    bias_gather_kernel<<<dim3(NTOK, NH), NTOK>>>(bias_table, rel_index);

    // 1) LN1 + window partition
    ln_kernel<true><<<TOK / 8, 256>>>(x, norm1_w, norm1_b, p_xw);

    // 2) QKV gemm (+ q scale)
    gemm_kernel<0><<<dim3(QKVN / 64, TOK / 128), 256>>>(p_xw, qkv_w, qkv_b, nullptr, p_qkv, QKVN, CDIM);

    // 3) window attention
    attn_kernel<<<dim3(NWIN, NH), 128>>>();

    // 4) proj gemm + window reverse + residual(x) -> g_x2 (spatial)
    gemm_kernel<1><<<dim3(CDIM / 64, TOK / 128), 256>>>(p_attn, proj_w, proj_b, x, p_x2, CDIM, CDIM);

    // 5) LN2 (spatial -> spatial)
    ln_kernel<false><<<TOK / 8, 256>>>(p_x2, norm2_w, norm2_b, p_xw);

    // 6) fc1 + exact GELU
    gemm_kernel<2><<<dim3(CH / 64, TOK / 128), 256>>>(p_xw, fc1_w, fc1_b, nullptr, p_h, CH, CDIM);

    // 7) fc2 + residual(g_x2) -> d_out
    gemm_kernel<3><<<dim3(CDIM / 64, TOK / 128), 256>>>(p_h, fc2_w, fc2_b, p_x2, out, CDIM, CH);

    (void)in_sizes; (void)n_in; (void)out_size;
}

// round 3
// speedup vs baseline: 2.3747x; 1.2227x over previous
#include <cuda_runtime.h>
#include <cuda_bf16.h>
#include <math.h>
#include <stdint.h>

// ---------------------------------------------------------------------------
// Problem constants
// ---------------------------------------------------------------------------
#define TOK   50176      // 2*8*56*56
#define CDIM  128
#define CH    512
#define NWIN  512        // 2 * 4*8*8
#define NTOK  98         // 2*7*7
#define NH    4
#define HD    32
#define QKVN  384

// ---------------------------------------------------------------------------
// Scratch (device globals: allocation-free, graph-capture safe)
// ---------------------------------------------------------------------------
__device__ float g_xw  [(size_t)TOK * CDIM];   // LN1 out (window order) / LN2 out (spatial)
__device__ float g_qkv [(size_t)TOK * QKVN];   // qkv, window order
__device__ float g_attn[(size_t)TOK * CDIM];   // attention out, window order
__device__ float g_x2  [(size_t)TOK * CDIM];   // x + proj (spatial)
__device__ float g_h   [(size_t)TOK * CH];     // fc1 output
__device__ float g_bias[NH * NTOK * NTOK];     // gathered attention bias

// ---------------------------------------------------------------------------
// index helpers
// ---------------------------------------------------------------------------
__device__ __forceinline__ long win_to_spatial(long row) {
    int w = (int)(row / NTOK);
    int n = (int)(row % NTOK);
    int b   = w >> 8;
    int rem = w & 255;
    int wdi = rem >> 6, whi = (rem >> 3) & 7, wwi = rem & 7;
    int zd = n / 49; int r2 = n % 49; int zh = r2 / 7, zw = r2 % 7;
    int d  = wdi * 2 + zd;
    int hh = whi * 7 + zh;
    int xx = wwi * 7 + zw;
    return (((long)(b * 8 + d) * 56) + hh) * 56 + xx;
}

__device__ __forceinline__ long spatial_to_win(long t) {
    int b  = (int)(t / 25088);
    int r  = (int)(t % 25088);
    int d  = r / 3136; r %= 3136;
    int hh = r / 56;
    int xx = r % 56;
    int widx = ((b * 4 + (d >> 1)) * 8 + hh / 7) * 8 + xx / 7;
    int n    = ((d & 1) * 7 + hh % 7) * 7 + xx % 7;
    return (long)widx * NTOK + n;
}

// ---------------------------------------------------------------------------
// async copy helpers
// ---------------------------------------------------------------------------
__device__ __forceinline__ void cp_async16(float* smem_dst, const float* gmem_src) {
    uint32_t s = (uint32_t)__cvta_generic_to_shared(smem_dst);
    asm volatile("cp.async.cg.shared.global [%0], [%1], 16;\n" :: "r"(s), "l"(gmem_src));
}
__device__ __forceinline__ void cp_commit() {
    asm volatile("cp.async.commit_group;\n");
}
template<int N>
__device__ __forceinline__ void cp_wait() {
    asm volatile("cp.async.wait_group %0;\n" :: "n"(N));
}

// ---------------------------------------------------------------------------
// tf32 mma.sync m16n8k8 (row.col), fp32 accumulate
// ---------------------------------------------------------------------------
__device__ __forceinline__ void mma_tf32(float c[4], const uint32_t a[4], const uint32_t b[2]) {
    asm volatile(
        "mma.sync.aligned.m16n8k8.row.col.f32.tf32.tf32.f32 "
        "{%0,%1,%2,%3}, {%4,%5,%6,%7}, {%8,%9}, {%0,%1,%2,%3};\n"
        : "+f"(c[0]), "+f"(c[1]), "+f"(c[2]), "+f"(c[3])
        : "r"(a[0]), "r"(a[1]), "r"(a[2]), "r"(a[3]), "r"(b[0]), "r"(b[1]));
}

// ---------------------------------------------------------------------------
// bias gather: g_bias[h][n][m] = bias_table[rel_index[n][m]][h]
// ---------------------------------------------------------------------------
__global__ void bias_gather_kernel(const float* __restrict__ bias_table,
                                   const int* __restrict__ rel_index) {
    int m = threadIdx.x;
    int n = blockIdx.x;
    int h = blockIdx.y;
    int idx = rel_index[n * NTOK + m];
    g_bias[(h * NTOK + n) * NTOK + m] = bias_table[idx * NH + h];
}

// ---------------------------------------------------------------------------
// LayerNorm over C=128: one warp per token, float4 per lane. 256 thr/block.
// ---------------------------------------------------------------------------
template<bool PERMUTE>
__global__ __launch_bounds__(256)
void ln_kernel(const float* __restrict__ in,
               const float* __restrict__ gam,
               const float* __restrict__ bet,
               float* __restrict__ out) {
    int warp = threadIdx.x >> 5;
    int lane = threadIdx.x & 31;
    long t = (long)blockIdx.x * 8 + warp;
    const float4 v = *(const float4*)(in + t * CDIM + lane * 4);
    float s  = v.x + v.y + v.z + v.w;
    float sq = v.x * v.x + v.y * v.y + v.z * v.z + v.w * v.w;
    #pragma unroll
    for (int o = 16; o; o >>= 1) {
        s  += __shfl_xor_sync(0xffffffffu, s,  o);
        sq += __shfl_xor_sync(0xffffffffu, sq, o);
    }
    float mean = s * (1.0f / CDIM);
    float var  = sq * (1.0f / CDIM) - mean * mean;
    float rstd = rsqrtf(var + 1e-5f);
    const float4 g = *(const float4*)(gam + lane * 4);
    const float4 b = *(const float4*)(bet + lane * 4);
    float4 y;
    y.x = (v.x - mean) * rstd * g.x + b.x;
    y.y = (v.y - mean) * rstd * g.y + b.y;
    y.z = (v.z - mean) * rstd * g.z + b.z;
    y.w = (v.w - mean) * rstd * g.w + b.w;
    long orow = PERMUTE ? spatial_to_win(t) : t;
    *(float4*)(out + orow * CDIM + lane * 4) = y;
}

// ---------------------------------------------------------------------------
// TF32 tensor-core GEMM v2: C[M,N] = A[M,K] @ W[N,K]^T (+ epilogue)
// Block tile 128x128, BK=32, 256 threads (8 warps: warpM 2 x warpN 4),
// warp tile 64x32. 2-stage cp.async pipeline.
// MODE 0: qkv   -> +bias; scale q-part; C [M,384]
// MODE 1: proj  -> +bias; spatial permute row; += resid(x); write g_x2
// MODE 2: fc1   -> +bias; exact-erf GELU; C [M,512]
// MODE 3: fc2   -> +bias; += resid(g_x2); write d_out
// ---------------------------------------------------------------------------
#define GSTR 36
#define G_TILE (128 * GSTR)
template<int MODE>
__global__ __launch_bounds__(256)
void gemm_kernel(const float* __restrict__ A,
                 const float* __restrict__ Wt,
                 const float* __restrict__ bias,
                 const float* __restrict__ resid,
                 float* __restrict__ C,
                 int N, int K) {
    extern __shared__ float smem[];
    float* Asb[2] = { smem,              smem + G_TILE };
    float* Wsb[2] = { smem + 2 * G_TILE, smem + 3 * G_TILE };

    const int tid  = threadIdx.x;
    const int lane = tid & 31;
    const int warp = tid >> 5;
    const int warpM = warp >> 2;        // 0..1
    const int warpN = warp & 3;         // 0..3
    const int gid = lane >> 2;          // 0..7
    const int tig = lane & 3;           // 0..3

    const long rowBase = (long)blockIdx.y * 128;
    const int  colBase = blockIdx.x * 128;

    float cc[4][4][4];
    #pragma unroll
    for (int mi = 0; mi < 4; mi++)
        #pragma unroll
        for (int ni = 0; ni < 4; ni++)
            #pragma unroll
            for (int e = 0; e < 4; e++) cc[mi][ni][e] = 0.f;

    const int m_ld  = tid >> 3;          // 0..31 per chunk of 256? (see below)
    const int kq_ld = (tid & 7) * 4;

    // tile loader: A rows 128 x 32k, W rows 128 x 32k (4 float4 each / thread)
    auto load_tile = [&](int buf, int k0) {
        #pragma unroll
        for (int r = 0; r < 4; r++) {
            int m = m_ld + r * 32;
            cp_async16(&Asb[buf][m * GSTR + kq_ld], A + (rowBase + m) * K + k0 + kq_ld);
        }
        #pragma unroll
        for (int r = 0; r < 4; r++) {
            int n = m_ld + r * 32;
            cp_async16(&Wsb[buf][n * GSTR + kq_ld], Wt + (long)(colBase + n) * K + k0 + kq_ld);
        }
    };

    const int nk = K >> 5;
    load_tile(0, 0);
    cp_commit();

    for (int it = 0; it < nk; it++) {
        if (it + 1 < nk) { load_tile((it + 1) & 1, (it + 1) * 32); cp_commit(); }
        if (it + 1 < nk) cp_wait<1>(); else cp_wait<0>();
        __syncthreads();

        const uint32_t* Asu = (const uint32_t*)Asb[it & 1];
        const uint32_t* Wsu = (const uint32_t*)Wsb[it & 1];
        #pragma unroll
        for (int ks = 0; ks < 4; ks++) {
            const int kk = ks * 8;
            uint32_t af[4][4];
            uint32_t bf[4][2];
            #pragma unroll
            for (int mi = 0; mi < 4; mi++) {
                int r = warpM * 64 + mi * 16 + gid;
                af[mi][0] = Asu[(r    ) * GSTR + kk + tig];
                af[mi][1] = Asu[(r + 8) * GSTR + kk + tig];
                af[mi][2] = Asu[(r    ) * GSTR + kk + tig + 4];
                af[mi][3] = Asu[(r + 8) * GSTR + kk + tig + 4];
            }
            #pragma unroll
            for (int ni = 0; ni < 4; ni++) {
                int n = warpN * 32 + ni * 8 + gid;
                bf[ni][0] = Wsu[n * GSTR + kk + tig];
                bf[ni][1] = Wsu[n * GSTR + kk + tig + 4];
            }
            #pragma unroll
            for (int mi = 0; mi < 4; mi++)
                #pragma unroll
                for (int ni = 0; ni < 4; ni++)
                    mma_tf32(cc[mi][ni], af[mi], bf[ni]);
        }
        __syncthreads();
    }

    // epilogue
    #pragma unroll
    for (int mi = 0; mi < 4; mi++) {
        #pragma unroll
        for (int half = 0; half < 2; half++) {
            long row  = rowBase + warpM * 64 + mi * 16 + gid + half * 8;
            long orow = (MODE == 1) ? win_to_spatial(row) : row;
            #pragma unroll
            for (int ni = 0; ni < 4; ni++) {
                int col = colBase + warpN * 32 + ni * 8 + 2 * tig;
                float v0 = cc[mi][ni][half * 2 + 0] + bias[col];
                float v1 = cc[mi][ni][half * 2 + 1] + bias[col + 1];
                if (MODE == 0) {
                    if (col < CDIM) { v0 *= 0.17677669529663687f; v1 *= 0.17677669529663687f; }
                }
                if (MODE == 2) {
                    v0 = 0.5f * v0 * (1.0f + erff(v0 * 0.70710678118654752f));
                    v1 = 0.5f * v1 * (1.0f + erff(v1 * 0.70710678118654752f));
                }
                if (MODE == 1 || MODE == 3) {
                    const float2 r = *(const float2*)(resid + orow * CDIM + col);
                    v0 += r.x; v1 += r.y;
                    *(float2*)(C + orow * CDIM + col) = make_float2(v0, v1);
                } else {
                    *(float2*)(C + row * (long)N + col) = make_float2(v0, v1);
                }
            }
        }
    }
}

// ---------------------------------------------------------------------------
// Tensor-core window attention: one block per (window, head). 4 warps.
// Warp w owns S/P/O rows [w*32, w*32+32). Rows padded to 128, cols to 104.
// smem: qs[128][36], ks[104][36] -- aliased by ps[128][108]; vs = V^T[32][108].
// Single-pass softmax (no max subtraction; scores are tiny, shift-invariant).
// ---------------------------------------------------------------------------
#define AQ 36
#define AP 108
__global__ __launch_bounds__(128)
void attn_kernel() {
    extern __shared__ float sm[];
    float* qs = sm;                       // [128][36]
    float* ks = sm + 128 * AQ;            // [104][36]
    float* ps = sm;                       // [128][108] (aliases qs+ks)
    float* vs = sm + 128 * AP;            // [32][108]  V^T

    const int w = blockIdx.x;
    const int h = blockIdx.y;
    const int tid  = threadIdx.x;
    const int warp = tid >> 5;
    const int lane = tid & 31;
    const int gid = lane >> 2;            // 0..7
    const int tig = lane & 3;             // 0..3

    const float* base = g_qkv + (size_t)w * NTOK * QKVN + h * HD;

    // load Q, K (coalesced float4) and V transposed
    for (int i = tid; i < NTOK * 8; i += 128) {
        int m = i >> 3, dq = (i & 7) * 4;
        *(float4*)&qs[m * AQ + dq] = *(const float4*)(base + m * QKVN + dq);
        *(float4*)&ks[m * AQ + dq] = *(const float4*)(base + m * QKVN + CDIM + dq);
        float4 v = *(const float4*)(base + m * QKVN + 2 * CDIM + dq);
        vs[(dq + 0) * AP + m] = v.x;
        vs[(dq + 1) * AP + m] = v.y;
        vs[(dq + 2) * AP + m] = v.z;
        vs[(dq + 3) * AP + m] = v.w;
    }
    // zero pads
    for (int i = tid; i < 30 * 8; i += 128) {   // qs rows 98..127
        int m = 98 + (i >> 3), dq = (i & 7) * 4;
        *(float4*)&qs[m * AQ + dq] = make_float4(0.f, 0.f, 0.f, 0.f);
    }
    if (tid < 6 * 8) {                          // ks rows 98..103
        int m = 98 + (tid >> 3), dq = (tid & 7) * 4;
        *(float4*)&ks[m * AQ + dq] = make_float4(0.f, 0.f, 0.f, 0.f);
    }
    for (int i = tid; i < 32 * 6; i += 128) {   // vs cols 98..103
        vs[(i / 6) * AP + 98 + (i % 6)] = 0.f;
    }
    __syncthreads();

    const uint32_t* qsu = (const uint32_t*)qs;
    const uint32_t* ksu = (const uint32_t*)ks;

    // ---- S = Q K^T : per warp 32 rows x 104 cols, K=32 ----
    float cc[2][13][4];
    #pragma unroll
    for (int mi = 0; mi < 2; mi++)
        #pragma unroll
        for (int ni = 0; ni < 13; ni++)
            #pragma unroll
            for (int e = 0; e < 4; e++) cc[mi][ni][e] = 0.f;

    #pragma unroll
    for (int ksx = 0; ksx < 4; ksx++) {
        const int kk = ksx * 8;
        uint32_t af[2][4];
        #pragma unroll
        for (int mi = 0; mi < 2; mi++) {
            int r = warp * 32 + mi * 16 + gid;
            af[mi][0] = qsu[(r    ) * AQ + kk + tig];
            af[mi][1] = qsu[(r + 8) * AQ + kk + tig];
            af[mi][2] = qsu[(r    ) * AQ + kk + tig + 4];
            af[mi][3] = qsu[(r + 8) * AQ + kk + tig + 4];
        }
        #pragma unroll
        for (int ni = 0; ni < 13; ni++) {
            int n = ni * 8 + gid;
            uint32_t bf[2];
            bf[0] = ksu[n * AQ + kk + tig];
            bf[1] = ksu[n * AQ + kk + tig + 4];
            mma_tf32(cc[0][ni], af[0], bf);
            mma_tf32(cc[1][ni], af[1], bf);
        }
    }

    // ---- softmax (in registers) ----
    float rsum[2][2] = {{0.f, 0.f}, {0.f, 0.f}};
    const float* gb = g_bias + h * NTOK * NTOK;
    #pragma unroll
    for (int mi = 0; mi < 2; mi++) {
        int r0 = warp * 32 + mi * 16 + gid;
        int r1 = r0 + 8;
        const float* b0p = gb + (r0 < NTOK ? r0 : NTOK - 1) * NTOK;
        const float* b1p = gb + (r1 < NTOK ? r1 : NTOK - 1) * NTOK;
        #pragma unroll
        for (int ni = 0; ni < 13; ni++) {
            int c0 = ni * 8 + 2 * tig;
            int c1 = c0 + 1;
            int cc0 = c0 < NTOK ? c0 : NTOK - 1;
            int cc1 = c1 < NTOK ? c1 : NTOK - 1;
            float e;
            e = (c0 < NTOK) ? __expf(cc[mi][ni][0] + b0p[cc0]) : 0.f; cc[mi][ni][0] = e; rsum[mi][0] += e;
            e = (c1 < NTOK) ? __expf(cc[mi][ni][1] + b0p[cc1]) : 0.f; cc[mi][ni][1] = e; rsum[mi][0] += e;
            e = (c0 < NTOK) ? __expf(cc[mi][ni][2] + b1p[cc0]) : 0.f; cc[mi][ni][2] = e; rsum[mi][1] += e;
            e = (c1 < NTOK) ? __expf(cc[mi][ni][3] + b1p[cc1]) : 0.f; cc[mi][ni][3] = e; rsum[mi][1] += e;
        }
    }
    float inv[2][2];
    #pragma unroll
    for (int mi = 0; mi < 2; mi++)
        #pragma unroll
        for (int hf = 0; hf < 2; hf++) {
            float s = rsum[mi][hf];
            s += __shfl_xor_sync(0xffffffffu, s, 1);
            s += __shfl_xor_sync(0xffffffffu, s, 2);
            inv[mi][hf] = 1.0f / s;
        }

    __syncthreads();   // all warps done reading qs/ks before ps overwrite

    // write normalized P (own rows only)
    #pragma unroll
    for (int mi = 0; mi < 2; mi++) {
        int r0 = warp * 32 + mi * 16 + gid;
        #pragma unroll
        for (int ni = 0; ni < 13; ni++) {
            int col = ni * 8 + 2 * tig;
            *(float2*)&ps[r0 * AP + col] =
                make_float2(cc[mi][ni][0] * inv[mi][0], cc[mi][ni][1] * inv[mi][0]);
            *(float2*)&ps[(r0 + 8) * AP + col] =
                make_float2(cc[mi][ni][2] * inv[mi][1], cc[mi][ni][3] * inv[mi][1]);
        }
    }
    __syncwarp();

    const uint32_t* psu = (const uint32_t*)ps;
    const uint32_t* vsu = (const uint32_t*)vs;

    // ---- O = P V : per warp 32 rows x 32 cols, K=104 ----
    float oo[2][4][4];
    #pragma unroll
    for (int mi = 0; mi < 2; mi++)
        #pragma unroll
        for (int ni = 0; ni < 4; ni++)
            #pragma unroll
            for (int e = 0; e < 4; e++) oo[mi][ni][e] = 0.f;

    #pragma unroll
    for (int k2 = 0; k2 < 13; k2++) {
        const int kk = k2 * 8;
        uint32_t af[2][4];
        #pragma unroll
        for (int mi = 0; mi < 2; mi++) {
            int r = warp * 32 + mi * 16 + gid;
            af[mi][0] = psu[(r    ) * AP + kk + tig];
            af[mi][1] = psu[(r + 8) * AP + kk + tig];
            af[mi][2] = psu[(r    ) * AP + kk + tig + 4];
            af[mi][3] = psu[(r + 8) * AP + kk + tig + 4];
        }
        #pragma unroll
        for (int ni = 0; ni < 4; ni++) {
            int n = ni * 8 + gid;
            uint32_t bf[2];
            bf[0] = vsu[n * AP + kk + tig];
            bf[1] = vsu[n * AP + kk + tig + 4];
            mma_tf32(oo[0][ni], af[0], bf);
            mma_tf32(oo[1][ni], af[1], bf);
        }
    }

    // store O rows < 98
    #pragma unroll
    for (int mi = 0; mi < 2; mi++) {
        #pragma unroll
        for (int hf = 0; hf < 2; hf++) {
            int row = warp * 32 + mi * 16 + gid + hf * 8;
            if (row < NTOK) {
                float* op = g_attn + ((size_t)w * NTOK + row) * CDIM + h * HD;
                #pragma unroll
                for (int ni = 0; ni < 4; ni++) {
                    int col = ni * 8 + 2 * tig;
                    *(float2*)(op + col) =
                        make_float2(oo[mi][ni][hf * 2], oo[mi][ni][hf * 2 + 1]);
                }
            }
        }
    }
}

// ---------------------------------------------------------------------------
// launcher
// ---------------------------------------------------------------------------
extern "C" void kernel_launch(void* const* d_in, const int* in_sizes, int n_in,
                              void* d_out, int out_size) {
    const float* x          = (const float*)d_in[0];
    const float* norm1_w    = (const float*)d_in[1];
    const float* norm1_b    = (const float*)d_in[2];
    const float* qkv_w      = (const float*)d_in[3];
    const float* qkv_b      = (const float*)d_in[4];
    const float* bias_table = (const float*)d_in[5];
    const float* proj_w     = (const float*)d_in[6];
    const float* proj_b     = (const float*)d_in[7];
    const float* norm2_w    = (const float*)d_in[8];
    const float* norm2_b    = (const float*)d_in[9];
    const float* fc1_w      = (const float*)d_in[10];
    const float* fc1_b      = (const float*)d_in[11];
    const float* fc2_w      = (const float*)d_in[12];
    const float* fc2_b      = (const float*)d_in[13];
    const int*   rel_index  = (const int*)d_in[14];
    float* out = (float*)d_out;

    float *p_xw, *p_qkv, *p_attn, *p_x2, *p_h;
    cudaGetSymbolAddress((void**)&p_xw,   g_xw);
    cudaGetSymbolAddress((void**)&p_qkv,  g_qkv);
    cudaGetSymbolAddress((void**)&p_attn, g_attn);
    cudaGetSymbolAddress((void**)&p_x2,   g_x2);
    cudaGetSymbolAddress((void**)&p_h,    g_h);

    const int GEMM_SMEM = 4 * G_TILE * (int)sizeof(float);       // 73728
    const int ATTN_SMEM = (128 * AP + 32 * AP) * (int)sizeof(float); // 69120
    cudaFuncSetAttribute(gemm_kernel<0>, cudaFuncAttributeMaxDynamicSharedMemorySize, GEMM_SMEM);
    cudaFuncSetAttribute(gemm_kernel<1>, cudaFuncAttributeMaxDynamicSharedMemorySize, GEMM_SMEM);
    cudaFuncSetAttribute(gemm_kernel<2>, cudaFuncAttributeMaxDynamicSharedMemorySize, GEMM_SMEM);
    cudaFuncSetAttribute(gemm_kernel<3>, cudaFuncAttributeMaxDynamicSharedMemorySize, GEMM_SMEM);
    cudaFuncSetAttribute(attn_kernel,    cudaFuncAttributeMaxDynamicSharedMemorySize, ATTN_SMEM);

    // 0) gather relative position bias
    bias_gather_kernel<<<dim3(NTOK, NH), NTOK>>>(bias_table, rel_index);

    // 1) LN1 + window partition
    ln_kernel<true><<<TOK / 8, 256>>>(x, norm1_w, norm1_b, p_xw);

    // 2) QKV gemm (+ q scale)
    gemm_kernel<0><<<dim3(QKVN / 128, TOK / 128), 256, GEMM_SMEM>>>(p_xw, qkv_w, qkv_b, nullptr, p_qkv, QKVN, CDIM);

    // 3) window attention (tensor cores)
    attn_kernel<<<dim3(NWIN, NH), 128, ATTN_SMEM>>>();

    // 4) proj gemm + window reverse + residual(x) -> g_x2 (spatial)
    gemm_kernel<1><<<dim3(CDIM / 128, TOK / 128), 256, GEMM_SMEM>>>(p_attn, proj_w, proj_b, x, p_x2, CDIM, CDIM);

    // 5) LN2
    ln_kernel<false><<<TOK / 8, 256>>>(p_x2, norm2_w, norm2_b, p_xw);

    // 6) fc1 + exact GELU
    gemm_kernel<2><<<dim3(CH / 128, TOK / 128), 256, GEMM_SMEM>>>(p_xw, fc1_w, fc1_b, nullptr, p_h, CH, CDIM);

    // 7) fc2 + residual(g_x2) -> d_out
    gemm_kernel<3><<<dim3(CDIM / 128, TOK / 128), 256, GEMM_SMEM>>>(p_h, fc2_w, fc2_b, p_x2, out, CDIM, CH);

    (void)in_sizes; (void)n_in; (void)out_size;
}

// round 4
// speedup vs baseline: 3.5652x; 1.5013x over previous
#include <cuda_runtime.h>
#include <cuda_bf16.h>
#include <math.h>
#include <stdint.h>

// ---------------------------------------------------------------------------
// Problem constants
// ---------------------------------------------------------------------------
#define TOK   50176      // 2*8*56*56
#define CDIM  128
#define CH    512
#define NWIN  512        // 2 * 4*8*8
#define NTOK  98         // 2*7*7
#define NH    4
#define HD    32
#define QKVN  384

typedef __nv_bfloat16  bf16;
typedef __nv_bfloat162 bf162;

// ---------------------------------------------------------------------------
// Scratch (device globals: allocation-free, graph-capture safe)
// ---------------------------------------------------------------------------
__device__ bf16  g_xw  [(size_t)TOK * CDIM];   // LN1 out (window order) / LN2 out (spatial)
__device__ bf16  g_qkv [(size_t)TOK * QKVN];   // qkv, window order
__device__ bf16  g_attn[(size_t)TOK * CDIM];   // attention out, window order
__device__ float g_x2  [(size_t)TOK * CDIM];   // x + proj (spatial, fp32)
__device__ bf16  g_h   [(size_t)TOK * CH];     // fc1 output
__device__ float g_bias[NH * NTOK * NTOK];     // gathered attention bias (fp32)
// bf16 weights
__device__ bf16  g_wq[QKVN * CDIM];
__device__ bf16  g_wp[CDIM * CDIM];
__device__ bf16  g_w1[CH * CDIM];
__device__ bf16  g_w2[CDIM * CH];

// ---------------------------------------------------------------------------
// index helpers
// ---------------------------------------------------------------------------
__device__ __forceinline__ long win_to_spatial(long row) {
    int w = (int)(row / NTOK);
    int n = (int)(row % NTOK);
    int b   = w >> 8;
    int rem = w & 255;
    int wdi = rem >> 6, whi = (rem >> 3) & 7, wwi = rem & 7;
    int zd = n / 49; int r2 = n % 49; int zh = r2 / 7, zw = r2 % 7;
    int d  = wdi * 2 + zd;
    int hh = whi * 7 + zh;
    int xx = wwi * 7 + zw;
    return (((long)(b * 8 + d) * 56) + hh) * 56 + xx;
}

__device__ __forceinline__ long spatial_to_win(long t) {
    int b  = (int)(t / 25088);
    int r  = (int)(t % 25088);
    int d  = r / 3136; r %= 3136;
    int hh = r / 56;
    int xx = r % 56;
    int widx = ((b * 4 + (d >> 1)) * 8 + hh / 7) * 8 + xx / 7;
    int n    = ((d & 1) * 7 + hh % 7) * 7 + xx % 7;
    return (long)widx * NTOK + n;
}

// ---------------------------------------------------------------------------
// async copy + ldmatrix + mma helpers
// ---------------------------------------------------------------------------
__device__ __forceinline__ void cp_async16(bf16* smem_dst, const bf16* gmem_src) {
    uint32_t s = (uint32_t)__cvta_generic_to_shared(smem_dst);
    asm volatile("cp.async.cg.shared.global [%0], [%1], 16;\n" :: "r"(s), "l"(gmem_src));
}
__device__ __forceinline__ void cp_commit() { asm volatile("cp.async.commit_group;\n"); }
template<int N>
__device__ __forceinline__ void cp_wait() { asm volatile("cp.async.wait_group %0;\n" :: "n"(N)); }

__device__ __forceinline__ void ldsm_x4(uint32_t r[4], const bf16* p) {
    uint32_t a = (uint32_t)__cvta_generic_to_shared(p);
    asm volatile("ldmatrix.sync.aligned.m8n8.x4.shared.b16 {%0,%1,%2,%3}, [%4];\n"
                 : "=r"(r[0]), "=r"(r[1]), "=r"(r[2]), "=r"(r[3]) : "r"(a));
}
__device__ __forceinline__ void ldsm_x4_t(uint32_t r[4], const bf16* p) {
    uint32_t a = (uint32_t)__cvta_generic_to_shared(p);
    asm volatile("ldmatrix.sync.aligned.m8n8.x4.trans.shared.b16 {%0,%1,%2,%3}, [%4];\n"
                 : "=r"(r[0]), "=r"(r[1]), "=r"(r[2]), "=r"(r[3]) : "r"(a));
}
__device__ __forceinline__ void mma_bf16(float c[4], const uint32_t a[4], const uint32_t b[2]) {
    asm volatile(
        "mma.sync.aligned.m16n8k16.row.col.f32.bf16.bf16.f32 "
        "{%0,%1,%2,%3}, {%4,%5,%6,%7}, {%8,%9}, {%0,%1,%2,%3};\n"
        : "+f"(c[0]), "+f"(c[1]), "+f"(c[2]), "+f"(c[3])
        : "r"(a[0]), "r"(a[1]), "r"(a[2]), "r"(a[3]), "r"(b[0]), "r"(b[1]));
}

// ---------------------------------------------------------------------------
// fused weight conversion fp32 -> bf16 (float4 granularity)
// segments: qkv_w 12288, proj_w 4096, fc1_w 16384, fc2_w 16384 (float4 units)
// ---------------------------------------------------------------------------
__global__ void cvt_weights_kernel(const float* __restrict__ wq,
                                   const float* __restrict__ wp,
                                   const float* __restrict__ w1,
                                   const float* __restrict__ w2) {
    int i = blockIdx.x * blockDim.x + threadIdx.x;   // float4 index, total 49152
    const float* src; bf16* dst; int off;
    if (i < 12288)      { src = wq; dst = g_wq; off = i; }
    else if (i < 16384) { src = wp; dst = g_wp; off = i - 12288; }
    else if (i < 32768) { src = w1; dst = g_w1; off = i - 16384; }
    else                { src = w2; dst = g_w2; off = i - 32768; }
    float4 v = *(const float4*)(src + off * 4);
    bf162 p0 = __float22bfloat162_rn(make_float2(v.x, v.y));
    bf162 p1 = __float22bfloat162_rn(make_float2(v.z, v.w));
    uint2 u = make_uint2(*(uint32_t*)&p0, *(uint32_t*)&p1);
    *(uint2*)(dst + off * 4) = u;
}

// ---------------------------------------------------------------------------
// bias gather: g_bias[h][n][m] = bias_table[rel_index[n][m]][h]
// ---------------------------------------------------------------------------
__global__ void bias_gather_kernel(const float* __restrict__ bias_table,
                                   const int* __restrict__ rel_index) {
    int m = threadIdx.x;
    int n = blockIdx.x;
    int h = blockIdx.y;
    int idx = rel_index[n * NTOK + m];
    g_bias[(h * NTOK + n) * NTOK + m] = bias_table[idx * NH + h];
}

// ---------------------------------------------------------------------------
// LayerNorm over C=128 (fp32 in, bf16 out): one warp per token.
// ---------------------------------------------------------------------------
template<bool PERMUTE>
__global__ __launch_bounds__(256)
void ln_kernel(const float* __restrict__ in,
               const float* __restrict__ gam,
               const float* __restrict__ bet,
               bf16* __restrict__ out) {
    int warp = threadIdx.x >> 5;
    int lane = threadIdx.x & 31;
    long t = (long)blockIdx.x * 8 + warp;
    const float4 v = *(const float4*)(in + t * CDIM + lane * 4);
    float s  = v.x + v.y + v.z + v.w;
    float sq = v.x * v.x + v.y * v.y + v.z * v.z + v.w * v.w;
    #pragma unroll
    for (int o = 16; o; o >>= 1) {
        s  += __shfl_xor_sync(0xffffffffu, s,  o);
        sq += __shfl_xor_sync(0xffffffffu, sq, o);
    }
    float mean = s * (1.0f / CDIM);
    float var  = sq * (1.0f / CDIM) - mean * mean;
    float rstd = rsqrtf(var + 1e-5f);
    const float4 g = *(const float4*)(gam + lane * 4);
    const float4 b = *(const float4*)(bet + lane * 4);
    bf162 p0 = __float22bfloat162_rn(make_float2((v.x - mean) * rstd * g.x + b.x,
                                                 (v.y - mean) * rstd * g.y + b.y));
    bf162 p1 = __float22bfloat162_rn(make_float2((v.z - mean) * rstd * g.z + b.z,
                                                 (v.w - mean) * rstd * g.w + b.w));
    long orow = PERMUTE ? spatial_to_win(t) : t;
    uint2 u = make_uint2(*(uint32_t*)&p0, *(uint32_t*)&p1);
    *(uint2*)(out + orow * CDIM + lane * 4) = u;
}

// ---------------------------------------------------------------------------
// BF16 tensor-core GEMM: C[M,N] = A[M,K] @ W[N,K]^T (+ epilogue)
// Block 128x128, BK=32 (halves), 256 threads (8 warps: 2x4), warp 64x32.
// m16n8k16 bf16 mma + ldmatrix.x4. 2-stage cp.async pipeline.
// MODE 0: qkv  -> +bias; scale q-part; bf16 out [M,384]
// MODE 1: proj -> +bias; permute row; += resid(x fp32); fp32 out g_x2
// MODE 2: fc1  -> +bias; exact GELU; bf16 out [M,512]
// MODE 3: fc2  -> +bias; += resid(g_x2); fp32 out d_out
// ---------------------------------------------------------------------------
#define GS 40                  // smem row stride (halves): 32 + 8 pad
#define G_STAGE (256 * GS)     // As(128)+Ws(128) rows per stage
template<int MODE>
__global__ __launch_bounds__(256)
void gemm_kernel(const bf16* __restrict__ A,
                 const bf16* __restrict__ Wt,
                 const float* __restrict__ bias,
                 const float* __restrict__ resid,
                 void* __restrict__ Cv,
                 int N, int K) {
    extern __shared__ bf16 sm[];
    bf16* Asb[2] = { sm,               sm + G_STAGE };
    bf16* Wsb[2] = { sm + 128 * GS,    sm + G_STAGE + 128 * GS };

    const int tid  = threadIdx.x;
    const int lane = tid & 31;
    const int warp = tid >> 5;
    const int warpM = warp >> 2;        // 0..1
    const int warpN = warp & 3;         // 0..3
    const int gid = lane >> 2;          // 0..7
    const int tig = lane & 3;           // 0..3

    const long rowBase = (long)blockIdx.y * 128;
    const int  colBase = blockIdx.x * 128;

    float cc[4][4][4];
    #pragma unroll
    for (int mi = 0; mi < 4; mi++)
        #pragma unroll
        for (int ni = 0; ni < 4; ni++)
            #pragma unroll
            for (int e = 0; e < 4; e++) cc[mi][ni][e] = 0.f;

    const int ld_row = tid >> 2;        // 0..63
    const int ld_kq  = (tid & 3) * 8;   // halves

    auto load_tile = [&](int buf, int k0) {
        #pragma unroll
        for (int r = 0; r < 2; r++) {
            int m = ld_row + r * 64;
            cp_async16(&Asb[buf][m * GS + ld_kq], A + (rowBase + m) * K + k0 + ld_kq);
        }
        #pragma unroll
        for (int r = 0; r < 2; r++) {
            int n = ld_row + r * 64;
            cp_async16(&Wsb[buf][n * GS + ld_kq], Wt + (long)(colBase + n) * K + k0 + ld_kq);
        }
    };

    const int nk = K >> 5;
    load_tile(0, 0);
    cp_commit();

    // ldmatrix lane-address components
    const int a_r = (lane & 7) + ((lane >> 3) & 1) * 8;   // row within 16
    const int a_k = (lane >> 4) * 8;                      // k half-offset
    const int b_n = (lane & 7) + (lane >> 4) * 8;         // n within 16
    const int b_k = ((lane >> 3) & 1) * 8;

    for (int it = 0; it < nk; it++) {
        if (it + 1 < nk) { load_tile((it + 1) & 1, (it + 1) * 32); cp_commit(); cp_wait<1>(); }
        else             { cp_wait<0>(); }
        __syncthreads();

        const bf16* As = Asb[it & 1];
        const bf16* Ws = Wsb[it & 1];
        #pragma unroll
        for (int ks = 0; ks < 2; ks++) {
            const int kk = ks * 16;
            uint32_t af[4][4];
            uint32_t bf[4][2];
            #pragma unroll
            for (int mi = 0; mi < 4; mi++) {
                int row0 = warpM * 64 + mi * 16;
                ldsm_x4(af[mi], As + (row0 + a_r) * GS + kk + a_k);
            }
            #pragma unroll
            for (int np = 0; np < 2; np++) {
                int n0 = warpN * 32 + np * 16;
                uint32_t r4[4];
                ldsm_x4(r4, Ws + (n0 + b_n) * GS + kk + b_k);
                bf[2 * np][0] = r4[0]; bf[2 * np][1] = r4[1];
                bf[2 * np + 1][0] = r4[2]; bf[2 * np + 1][1] = r4[3];
            }
            #pragma unroll
            for (int mi = 0; mi < 4; mi++)
                #pragma unroll
                for (int ni = 0; ni < 4; ni++)
                    mma_bf16(cc[mi][ni], af[mi], bf[ni]);
        }
        __syncthreads();
    }

    // epilogue
    #pragma unroll
    for (int mi = 0; mi < 4; mi++) {
        #pragma unroll
        for (int half = 0; half < 2; half++) {
            long row  = rowBase + warpM * 64 + mi * 16 + gid + half * 8;
            long orow = (MODE == 1) ? win_to_spatial(row) : row;
            #pragma unroll
            for (int ni = 0; ni < 4; ni++) {
                int col = colBase + warpN * 32 + ni * 8 + 2 * tig;
                float v0 = cc[mi][ni][half * 2 + 0] + bias[col];
                float v1 = cc[mi][ni][half * 2 + 1] + bias[col + 1];
                if (MODE == 0) {
                    if (col < CDIM) { v0 *= 0.17677669529663687f; v1 *= 0.17677669529663687f; }
                }
                if (MODE == 2) {
                    v0 = 0.5f * v0 * (1.0f + erff(v0 * 0.70710678118654752f));
                    v1 = 0.5f * v1 * (1.0f + erff(v1 * 0.70710678118654752f));
                }
                if (MODE == 1 || MODE == 3) {
                    float* C = (float*)Cv;
                    const float2 r = *(const float2*)(resid + orow * CDIM + col);
                    *(float2*)(C + orow * CDIM + col) = make_float2(v0 + r.x, v1 + r.y);
                } else {
                    bf16* C = (bf16*)Cv;
                    bf162 p = __float22bfloat162_rn(make_float2(v0, v1));
                    *(bf162*)(C + row * (long)N + col) = p;
                }
            }
        }
    }
}

// ---------------------------------------------------------------------------
// BF16 tensor-core window attention: one block per (window, head). 4 warps.
// Warp w owns rows [w*32, w*32+32). N padded to 112, k(S)=32, k(O)=112.
// smem (bf16): qs[128][40], ks[112][40], vsr[112][40] (V row-major), ps[128][120].
// Single-pass softmax in fp32 registers; P normalized then stored bf16.
// ---------------------------------------------------------------------------
#define AQS 40
#define PSS 120
#define NPAD 112
__global__ __launch_bounds__(128)
void attn_kernel() {
    extern __shared__ bf16 asm_[];
    bf16* qs  = asm_;                          // [128][40]
    bf16* ks  = qs  + 128 * AQS;               // [112][40]
    bf16* vsr = ks  + NPAD * AQS;              // [112][40]
    bf16* ps  = vsr + NPAD * AQS;              // [128][120]

    const int w = blockIdx.x;
    const int h = blockIdx.y;
    const int tid  = threadIdx.x;
    const int warp = tid >> 5;
    const int lane = tid & 31;
    const int gid = lane >> 2;
    const int tig = lane & 3;

    const bf16* base = g_qkv + (size_t)w * NTOK * QKVN + h * HD;

    // load Q, K, V (16B chunks, coalesced)
    for (int i = tid; i < NTOK * 4; i += 128) {
        int m = i >> 2, c = (i & 3) * 8;
        *(uint4*)&qs [m * AQS + c] = *(const uint4*)(base + m * QKVN + c);
        *(uint4*)&ks [m * AQS + c] = *(const uint4*)(base + m * QKVN + CDIM + c);
        *(uint4*)&vsr[m * AQS + c] = *(const uint4*)(base + m * QKVN + 2 * CDIM + c);
    }
    // zero pads (rows 98.. of each)
    const uint4 z4 = make_uint4(0, 0, 0, 0);
    for (int i = tid; i < 30 * 4; i += 128) {
        int m = 98 + (i >> 2), c = (i & 3) * 8;
        *(uint4*)&qs[m * AQS + c] = z4;
        if (m < NPAD) {
            *(uint4*)&ks [m * AQS + c] = z4;
            *(uint4*)&vsr[m * AQS + c] = z4;
        }
    }
    __syncthreads();

    const int a_r = (lane & 7) + ((lane >> 3) & 1) * 8;
    const int a_k = (lane >> 4) * 8;
    const int b_n = (lane & 7) + (lane >> 4) * 8;
    const int b_k = ((lane >> 3) & 1) * 8;
    const int t_r = (lane & 7) + ((lane >> 3) & 1) * 8;   // trans: row = k
    const int t_c = (lane >> 4) * 8;                      // trans: col = n

    // ---- S = Q K^T : 32 rows x 112 cols, k=32 (2 k-steps) ----
    float cc[2][14][4];
    #pragma unroll
    for (int mi = 0; mi < 2; mi++)
        #pragma unroll
        for (int ni = 0; ni < 14; ni++)
            #pragma unroll
            for (int e = 0; e < 4; e++) cc[mi][ni][e] = 0.f;

    #pragma unroll
    for (int ksx = 0; ksx < 2; ksx++) {
        const int kk = ksx * 16;
        uint32_t af[2][4];
        #pragma unroll
        for (int mi = 0; mi < 2; mi++)
            ldsm_x4(af[mi], qs + (warp * 32 + mi * 16 + a_r) * AQS + kk + a_k);
        #pragma unroll
        for (int np = 0; np < 7; np++) {
            uint32_t r4[4];
            ldsm_x4(r4, ks + (np * 16 + b_n) * AQS + kk + b_k);
            uint32_t b0[2] = { r4[0], r4[1] };
            uint32_t b1[2] = { r4[2], r4[3] };
            mma_bf16(cc[0][2 * np],     af[0], b0);
            mma_bf16(cc[1][2 * np],     af[1], b0);
            mma_bf16(cc[0][2 * np + 1], af[0], b1);
            mma_bf16(cc[1][2 * np + 1], af[1], b1);
        }
    }

    // ---- softmax (fp32 regs, no max subtraction: scores are tiny) ----
    float rsum[2][2] = {{0.f, 0.f}, {0.f, 0.f}};
    const float* gb = g_bias + h * NTOK * NTOK;
    #pragma unroll
    for (int mi = 0; mi < 2; mi++) {
        int r0 = warp * 32 + mi * 16 + gid;
        int r1 = r0 + 8;
        const float* b0p = gb + (r0 < NTOK ? r0 : NTOK - 1) * NTOK;
        const float* b1p = gb + (r1 < NTOK ? r1 : NTOK - 1) * NTOK;
        #pragma unroll
        for (int ni = 0; ni < 14; ni++) {
            int c0 = ni * 8 + 2 * tig;
            int c1 = c0 + 1;
            int cc0 = c0 < NTOK ? c0 : NTOK - 1;
            int cc1 = c1 < NTOK ? c1 : NTOK - 1;
            float e;
            e = (c0 < NTOK) ? __expf(cc[mi][ni][0] + b0p[cc0]) : 0.f; cc[mi][ni][0] = e; rsum[mi][0] += e;
            e = (c1 < NTOK) ? __expf(cc[mi][ni][1] + b0p[cc1]) : 0.f; cc[mi][ni][1] = e; rsum[mi][0] += e;
            e = (c0 < NTOK) ? __expf(cc[mi][ni][2] + b1p[cc0]) : 0.f; cc[mi][ni][2] = e; rsum[mi][1] += e;
            e = (c1 < NTOK) ? __expf(cc[mi][ni][3] + b1p[cc1]) : 0.f; cc[mi][ni][3] = e; rsum[mi][1] += e;
        }
    }
    float inv[2][2];
    #pragma unroll
    for (int mi = 0; mi < 2; mi++)
        #pragma unroll
        for (int hf = 0; hf < 2; hf++) {
            float s = rsum[mi][hf];
            s += __shfl_xor_sync(0xffffffffu, s, 1);
            s += __shfl_xor_sync(0xffffffffu, s, 2);
            inv[mi][hf] = 1.0f / s;
        }

    // write normalized P as bf16 (own rows only -> warp-local sync suffices)
    #pragma unroll
    for (int mi = 0; mi < 2; mi++) {
        int r0 = warp * 32 + mi * 16 + gid;
        #pragma unroll
        for (int ni = 0; ni < 14; ni++) {
            int col = ni * 8 + 2 * tig;
            bf162 p0 = __float22bfloat162_rn(
                make_float2(cc[mi][ni][0] * inv[mi][0], cc[mi][ni][1] * inv[mi][0]));
            bf162 p1 = __float22bfloat162_rn(
                make_float2(cc[mi][ni][2] * inv[mi][1], cc[mi][ni][3] * inv[mi][1]));
            *(bf162*)&ps[r0 * PSS + col]       = p0;
            *(bf162*)&ps[(r0 + 8) * PSS + col] = p1;
        }
    }
    __syncwarp();

    // ---- O = P V : 32 rows x 32 cols, k=112 (7 k-steps) ----
    float oo[2][4][4];
    #pragma unroll
    for (int mi = 0; mi < 2; mi++)
        #pragma unroll
        for (int ni = 0; ni < 4; ni++)
            #pragma unroll
            for (int e = 0; e < 4; e++) oo[mi][ni][e] = 0.f;

    #pragma unroll
    for (int k2 = 0; k2 < 7; k2++) {
        const int kk = k2 * 16;
        uint32_t af[2][4];
        #pragma unroll
        for (int mi = 0; mi < 2; mi++)
            ldsm_x4(af[mi], ps + (warp * 32 + mi * 16 + a_r) * PSS + kk + a_k);
        #pragma unroll
        for (int np = 0; np < 2; np++) {
            int n0 = np * 16;
            uint32_t r4[4];
            ldsm_x4_t(r4, vsr + (kk + t_r) * AQS + n0 + t_c);
            uint32_t b0[2] = { r4[0], r4[1] };
            uint32_t b1[2] = { r4[2], r4[3] };
            mma_bf16(oo[0][2 * np],     af[0], b0);
            mma_bf16(oo[1][2 * np],     af[1], b0);
            mma_bf16(oo[0][2 * np + 1], af[0], b1);
            mma_bf16(oo[1][2 * np + 1], af[1], b1);
        }
    }

    // store O (bf16) rows < 98
    #pragma unroll
    for (int mi = 0; mi < 2; mi++) {
        #pragma unroll
        for (int hf = 0; hf < 2; hf++) {
            int row = warp * 32 + mi * 16 + gid + hf * 8;
            if (row < NTOK) {
                bf16* op = g_attn + ((size_t)w * NTOK + row) * CDIM + h * HD;
                #pragma unroll
                for (int ni = 0; ni < 4; ni++) {
                    int col = ni * 8 + 2 * tig;
                    bf162 p = __float22bfloat162_rn(
                        make_float2(oo[mi][ni][hf * 2], oo[mi][ni][hf * 2 + 1]));
                    *(bf162*)(op + col) = p;
                }
            }
        }
    }
}

// ---------------------------------------------------------------------------
// launcher
// ---------------------------------------------------------------------------
extern "C" void kernel_launch(void* const* d_in, const int* in_sizes, int n_in,
                              void* d_out, int out_size) {
    const float* x          = (const float*)d_in[0];
    const float* norm1_w    = (const float*)d_in[1];
    const float* norm1_b    = (const float*)d_in[2];
    const float* qkv_w      = (const float*)d_in[3];
    const float* qkv_b      = (const float*)d_in[4];
    const float* bias_table = (const float*)d_in[5];
    const float* proj_w     = (const float*)d_in[6];
    const float* proj_b     = (const float*)d_in[7];
    const float* norm2_w    = (const float*)d_in[8];
    const float* norm2_b    = (const float*)d_in[9];
    const float* fc1_w      = (const float*)d_in[10];
    const float* fc1_b      = (const float*)d_in[11];
    const float* fc2_w      = (const float*)d_in[12];
    const float* fc2_b      = (const float*)d_in[13];
    const int*   rel_index  = (const int*)d_in[14];
    float* out = (float*)d_out;

    bf16 *p_xw, *p_qkv, *p_attn, *p_h;
    bf16 *p_wq, *p_wp, *p_w1, *p_w2;
    float *p_x2;
    cudaGetSymbolAddress((void**)&p_xw,   g_xw);
    cudaGetSymbolAddress((void**)&p_qkv,  g_qkv);
    cudaGetSymbolAddress((void**)&p_attn, g_attn);
    cudaGetSymbolAddress((void**)&p_x2,   g_x2);
    cudaGetSymbolAddress((void**)&p_h,    g_h);
    cudaGetSymbolAddress((void**)&p_wq,   g_wq);
    cudaGetSymbolAddress((void**)&p_wp,   g_wp);
    cudaGetSymbolAddress((void**)&p_w1,   g_w1);
    cudaGetSymbolAddress((void**)&p_w2,   g_w2);

    const int GEMM_SMEM = 2 * G_STAGE * (int)sizeof(bf16);   // 40960
    const int ATTN_SMEM = (128 * AQS + 2 * NPAD * AQS + 128 * PSS) * (int)sizeof(bf16); // 58880
    cudaFuncSetAttribute(gemm_kernel<0>, cudaFuncAttributeMaxDynamicSharedMemorySize, GEMM_SMEM);
    cudaFuncSetAttribute(gemm_kernel<1>, cudaFuncAttributeMaxDynamicSharedMemorySize, GEMM_SMEM);
    cudaFuncSetAttribute(gemm_kernel<2>, cudaFuncAttributeMaxDynamicSharedMemorySize, GEMM_SMEM);
    cudaFuncSetAttribute(gemm_kernel<3>, cudaFuncAttributeMaxDynamicSharedMemorySize, GEMM_SMEM);
    cudaFuncSetAttribute(attn_kernel,    cudaFuncAttributeMaxDynamicSharedMemorySize, ATTN_SMEM);

    // 0) weight conversion + bias gather
    cvt_weights_kernel<<<49152 / 256, 256>>>(qkv_w, proj_w, fc1_w, fc2_w);
    bias_gather_kernel<<<dim3(NTOK, NH), NTOK>>>(bias_table, rel_index);

    // 1) LN1 + window partition (fp32 -> bf16)
    ln_kernel<true><<<TOK / 8, 256>>>(x, norm1_w, norm1_b, p_xw);

    // 2) QKV gemm (+ q scale), bf16 out
    gemm_kernel<0><<<dim3(QKVN / 128, TOK / 128), 256, GEMM_SMEM>>>(p_xw, p_wq, qkv_b, nullptr, p_qkv, QKVN, CDIM);

    // 3) window attention (bf16 tensor cores)
    attn_kernel<<<dim3(NWIN, NH), 128, ATTN_SMEM>>>();

    // 4) proj gemm + window reverse + residual(x) -> g_x2 (fp32 spatial)
    gemm_kernel<1><<<dim3(CDIM / 128, TOK / 128), 256, GEMM_SMEM>>>(p_attn, p_wp, proj_b, x, p_x2, CDIM, CDIM);

    // 5) LN2 (fp32 -> bf16)
    ln_kernel<false><<<TOK / 8, 256>>>(p_x2, norm2_w, norm2_b, p_xw);

    // 6) fc1 + exact GELU, bf16 out
    gemm_kernel<2><<<dim3(CH / 128, TOK / 128), 256, GEMM_SMEM>>>(p_xw, p_w1, fc1_b, nullptr, p_h, CH, CDIM);

    // 7) fc2 + residual(g_x2) -> d_out (fp32)
    gemm_kernel<3><<<dim3(CDIM / 128, TOK / 128), 256, GEMM_SMEM>>>(p_h, p_w2, fc2_b, p_x2, out, CDIM, CH);

    (void)in_sizes; (void)n_in; (void)out_size;
}

// round 5
// speedup vs baseline: 3.9558x; 1.1096x over previous
#include <cuda_runtime.h>
#include <cuda_bf16.h>
#include <math.h>
#include <stdint.h>

// ---------------------------------------------------------------------------
// Problem constants
// ---------------------------------------------------------------------------
#define TOK   50176      // 2*8*56*56
#define CDIM  128
#define CH    512
#define NWIN  512        // 2 * 4*8*8
#define NTOK  98         // 2*7*7
#define NH    4
#define HD    32
#define QKVN  384

typedef __nv_bfloat16  bf16;
typedef __nv_bfloat162 bf162;

// ---------------------------------------------------------------------------
// Scratch (device globals: allocation-free, graph-capture safe)
// ---------------------------------------------------------------------------
__device__ bf16  g_xw  [(size_t)TOK * CDIM];   // LN1 out (window order) / LN2 out (spatial)
__device__ bf16  g_qkv [(size_t)TOK * QKVN];   // qkv, window order
__device__ bf16  g_attn[(size_t)TOK * CDIM];   // attention out, window order
__device__ float g_x2  [(size_t)TOK * CDIM];   // x + proj (spatial, fp32)
__device__ bf16  g_h   [(size_t)TOK * CH];     // fc1 output
__device__ float g_bias[NH * NTOK * NTOK];     // gathered attention bias (fp32)
// bf16 weights
__device__ bf16  g_wq[QKVN * CDIM];
__device__ bf16  g_wp[CDIM * CDIM];
__device__ bf16  g_w1[CH * CDIM];
__device__ bf16  g_w2[CDIM * CH];

// ---------------------------------------------------------------------------
// index helpers
// ---------------------------------------------------------------------------
__device__ __forceinline__ long win_to_spatial(long row) {
    int w = (int)(row / NTOK);
    int n = (int)(row % NTOK);
    int b   = w >> 8;
    int rem = w & 255;
    int wdi = rem >> 6, whi = (rem >> 3) & 7, wwi = rem & 7;
    int zd = n / 49; int r2 = n % 49; int zh = r2 / 7, zw = r2 % 7;
    int d  = wdi * 2 + zd;
    int hh = whi * 7 + zh;
    int xx = wwi * 7 + zw;
    return (((long)(b * 8 + d) * 56) + hh) * 56 + xx;
}

__device__ __forceinline__ long spatial_to_win(long t) {
    int b  = (int)(t / 25088);
    int r  = (int)(t % 25088);
    int d  = r / 3136; r %= 3136;
    int hh = r / 56;
    int xx = r % 56;
    int widx = ((b * 4 + (d >> 1)) * 8 + hh / 7) * 8 + xx / 7;
    int n    = ((d & 1) * 7 + hh % 7) * 7 + xx % 7;
    return (long)widx * NTOK + n;
}

// ---------------------------------------------------------------------------
// async copy + ldmatrix + mma helpers
// ---------------------------------------------------------------------------
__device__ __forceinline__ void cp_async16(bf16* smem_dst, const bf16* gmem_src) {
    uint32_t s = (uint32_t)__cvta_generic_to_shared(smem_dst);
    asm volatile("cp.async.cg.shared.global [%0], [%1], 16;\n" :: "r"(s), "l"(gmem_src));
}
__device__ __forceinline__ void cp_commit() { asm volatile("cp.async.commit_group;\n"); }
template<int N>
__device__ __forceinline__ void cp_wait() { asm volatile("cp.async.wait_group %0;\n" :: "n"(N)); }

__device__ __forceinline__ void ldsm_x4(uint32_t r[4], const bf16* p) {
    uint32_t a = (uint32_t)__cvta_generic_to_shared(p);
    asm volatile("ldmatrix.sync.aligned.m8n8.x4.shared.b16 {%0,%1,%2,%3}, [%4];\n"
                 : "=r"(r[0]), "=r"(r[1]), "=r"(r[2]), "=r"(r[3]) : "r"(a));
}
__device__ __forceinline__ void ldsm_x4_t(uint32_t r[4], const bf16* p) {
    uint32_t a = (uint32_t)__cvta_generic_to_shared(p);
    asm volatile("ldmatrix.sync.aligned.m8n8.x4.trans.shared.b16 {%0,%1,%2,%3}, [%4];\n"
                 : "=r"(r[0]), "=r"(r[1]), "=r"(r[2]), "=r"(r[3]) : "r"(a));
}
__device__ __forceinline__ void mma_bf16(float c[4], const uint32_t a[4], const uint32_t b[2]) {
    asm volatile(
        "mma.sync.aligned.m16n8k16.row.col.f32.bf16.bf16.f32 "
        "{%0,%1,%2,%3}, {%4,%5,%6,%7}, {%8,%9}, {%0,%1,%2,%3};\n"
        : "+f"(c[0]), "+f"(c[1]), "+f"(c[2]), "+f"(c[3])
        : "r"(a[0]), "r"(a[1]), "r"(a[2]), "r"(a[3]), "r"(b[0]), "r"(b[1]));
}

// ---------------------------------------------------------------------------
// fused weight conversion fp32 -> bf16 (float4 granularity)
// ---------------------------------------------------------------------------
__global__ void cvt_weights_kernel(const float* __restrict__ wq,
                                   const float* __restrict__ wp,
                                   const float* __restrict__ w1,
                                   const float* __restrict__ w2) {
    int i = blockIdx.x * blockDim.x + threadIdx.x;   // float4 index, total 49152
    const float* src; bf16* dst; int off;
    if (i < 12288)      { src = wq; dst = g_wq; off = i; }
    else if (i < 16384) { src = wp; dst = g_wp; off = i - 12288; }
    else if (i < 32768) { src = w1; dst = g_w1; off = i - 16384; }
    else                { src = w2; dst = g_w2; off = i - 32768; }
    float4 v = *(const float4*)(src + off * 4);
    bf162 p0 = __float22bfloat162_rn(make_float2(v.x, v.y));
    bf162 p1 = __float22bfloat162_rn(make_float2(v.z, v.w));
    uint2 u = make_uint2(*(uint32_t*)&p0, *(uint32_t*)&p1);
    *(uint2*)(dst + off * 4) = u;
}

// ---------------------------------------------------------------------------
// bias gather: g_bias[h][n][m] = bias_table[rel_index[n][m]][h]
// ---------------------------------------------------------------------------
__global__ void bias_gather_kernel(const float* __restrict__ bias_table,
                                   const int* __restrict__ rel_index) {
    int m = threadIdx.x;
    int n = blockIdx.x;
    int h = blockIdx.y;
    int idx = rel_index[n * NTOK + m];
    g_bias[(h * NTOK + n) * NTOK + m] = bias_table[idx * NH + h];
}

// ---------------------------------------------------------------------------
// LayerNorm over C=128 (fp32 in, bf16 out): one warp per token.
// ---------------------------------------------------------------------------
template<bool PERMUTE>
__global__ __launch_bounds__(256)
void ln_kernel(const float* __restrict__ in,
               const float* __restrict__ gam,
               const float* __restrict__ bet,
               bf16* __restrict__ out) {
    int warp = threadIdx.x >> 5;
    int lane = threadIdx.x & 31;
    long t = (long)blockIdx.x * 8 + warp;
    const float4 v = *(const float4*)(in + t * CDIM + lane * 4);
    float s  = v.x + v.y + v.z + v.w;
    float sq = v.x * v.x + v.y * v.y + v.z * v.z + v.w * v.w;
    #pragma unroll
    for (int o = 16; o; o >>= 1) {
        s  += __shfl_xor_sync(0xffffffffu, s,  o);
        sq += __shfl_xor_sync(0xffffffffu, sq, o);
    }
    float mean = s * (1.0f / CDIM);
    float var  = sq * (1.0f / CDIM) - mean * mean;
    float rstd = rsqrtf(var + 1e-5f);
    const float4 g = *(const float4*)(gam + lane * 4);
    const float4 b = *(const float4*)(bet + lane * 4);
    bf162 p0 = __float22bfloat162_rn(make_float2((v.x - mean) * rstd * g.x + b.x,
                                                 (v.y - mean) * rstd * g.y + b.y));
    bf162 p1 = __float22bfloat162_rn(make_float2((v.z - mean) * rstd * g.z + b.z,
                                                 (v.w - mean) * rstd * g.w + b.w));
    long orow = PERMUTE ? spatial_to_win(t) : t;
    uint2 u = make_uint2(*(uint32_t*)&p0, *(uint32_t*)&p1);
    *(uint2*)(out + orow * CDIM + lane * 4) = u;
}

// ---------------------------------------------------------------------------
// BF16 tensor-core GEMM v3: C[M,N] = A[M,K] @ W[N,K]^T (+ epilogue)
// Block 128x128, BK=32, 3-stage cp.async pipeline, ONE sync per k-iter.
// 256 threads (8 warps: 2x4), warp tile 64x32, m16n8k16 + ldmatrix.x4.
// MODE 0: qkv  -> +bias; scale q-part; bf16 out [M,384]
// MODE 1: proj -> +bias; permute; += resid(x); fp32 g_x2  AND fused LN2 -> bf16 g_xw
// MODE 2: fc1  -> +bias; exact GELU; bf16 out [M,512]
// MODE 3: fc2  -> +bias; += resid(g_x2); fp32 out d_out
// ---------------------------------------------------------------------------
#define GS 40                  // smem row stride (halves): 32 + 8 pad
#define G_STAGE (256 * GS)     // As(128)+Ws(128) rows per stage
template<int MODE, int KT>
__global__ __launch_bounds__(256, 2)
void gemm_kernel(const bf16* __restrict__ A,
                 const bf16* __restrict__ Wt,
                 const float* __restrict__ bias,
                 const float* __restrict__ resid,
                 const float* __restrict__ gam,
                 const float* __restrict__ bet,
                 void* __restrict__ Cv,
                 int N) {
    extern __shared__ bf16 sm[];
    bf16* Asb[3] = { sm, sm + G_STAGE, sm + 2 * G_STAGE };
    bf16* Wsb[3] = { sm + 128 * GS, sm + G_STAGE + 128 * GS, sm + 2 * G_STAGE + 128 * GS };

    const int tid  = threadIdx.x;
    const int lane = tid & 31;
    const int warp = tid >> 5;
    const int warpM = warp >> 2;        // 0..1
    const int warpN = warp & 3;         // 0..3
    const int gid = lane >> 2;          // 0..7
    const int tig = lane & 3;           // 0..3

    const long rowBase = (long)blockIdx.y * 128;
    const int  colBase = blockIdx.x * 128;
    const int  K = KT;

    float cc[4][4][4];
    #pragma unroll
    for (int mi = 0; mi < 4; mi++)
        #pragma unroll
        for (int ni = 0; ni < 4; ni++)
            #pragma unroll
            for (int e = 0; e < 4; e++) cc[mi][ni][e] = 0.f;

    const int ld_row = tid >> 2;        // 0..63
    const int ld_kq  = (tid & 3) * 8;   // halves

    auto load_tile = [&](int buf, int k0) {
        #pragma unroll
        for (int r = 0; r < 2; r++) {
            int m = ld_row + r * 64;
            cp_async16(&Asb[buf][m * GS + ld_kq], A + (rowBase + m) * K + k0 + ld_kq);
        }
        #pragma unroll
        for (int r = 0; r < 2; r++) {
            int n = ld_row + r * 64;
            cp_async16(&Wsb[buf][n * GS + ld_kq], Wt + (long)(colBase + n) * K + k0 + ld_kq);
        }
    };

    constexpr int nk = KT / 32;
    load_tile(0, 0);  cp_commit();
    load_tile(1, 32); cp_commit();

    // ldmatrix lane-address components
    const int a_r = (lane & 7) + ((lane >> 3) & 1) * 8;
    const int a_k = (lane >> 4) * 8;
    const int b_n = (lane & 7) + (lane >> 4) * 8;
    const int b_k = ((lane >> 3) & 1) * 8;

    #pragma unroll
    for (int it = 0; it < nk; it++) {
        cp_wait<1>();
        __syncthreads();
        // prefetch stage it+2 (safe: every warp finished reading stage (it-1)%3)
        if (it + 2 < nk) load_tile((it + 2) % 3, (it + 2) * 32);
        cp_commit();

        const bf16* As = Asb[it % 3];
        const bf16* Ws = Wsb[it % 3];
        #pragma unroll
        for (int ks = 0; ks < 2; ks++) {
            const int kk = ks * 16;
            uint32_t af[4][4];
            uint32_t bf[4][2];
            #pragma unroll
            for (int mi = 0; mi < 4; mi++)
                ldsm_x4(af[mi], As + (warpM * 64 + mi * 16 + a_r) * GS + kk + a_k);
            #pragma unroll
            for (int np = 0; np < 2; np++) {
                uint32_t r4[4];
                ldsm_x4(r4, Ws + (warpN * 32 + np * 16 + b_n) * GS + kk + b_k);
                bf[2 * np][0] = r4[0]; bf[2 * np][1] = r4[1];
                bf[2 * np + 1][0] = r4[2]; bf[2 * np + 1][1] = r4[3];
            }
            #pragma unroll
            for (int mi = 0; mi < 4; mi++)
                #pragma unroll
                for (int ni = 0; ni < 4; ni++)
                    mma_bf16(cc[mi][ni], af[mi], bf[ni]);
        }
    }

    if (MODE == 1) {
        // fused: x2 = resid + proj_out (+bias), write fp32 g_x2;
        // then LayerNorm(x2) over full 128-col rows -> bf16 g_xw.
        __syncthreads();                 // all warps done with smem stages
        float* red = (float*)sm;         // [128][2] row sums
        if (tid < 128) { red[2 * tid] = 0.f; red[2 * tid + 1] = 0.f; }
        __syncthreads();

        long orows[4][2];
        float* C = (float*)Cv;
        #pragma unroll
        for (int mi = 0; mi < 4; mi++) {
            #pragma unroll
            for (int half = 0; half < 2; half++) {
                int rloc = warpM * 64 + mi * 16 + gid + half * 8;
                long orow = win_to_spatial(rowBase + rloc);
                orows[mi][half] = orow;
                float s = 0.f, sq = 0.f;
                #pragma unroll
                for (int ni = 0; ni < 4; ni++) {
                    int col = warpN * 32 + ni * 8 + 2 * tig;
                    const float2 r = *(const float2*)(resid + orow * CDIM + col);
                    float v0 = cc[mi][ni][half * 2 + 0] + bias[col]     + r.x;
                    float v1 = cc[mi][ni][half * 2 + 1] + bias[col + 1] + r.y;
                    cc[mi][ni][half * 2 + 0] = v0;
                    cc[mi][ni][half * 2 + 1] = v1;
                    *(float2*)(C + orow * CDIM + col) = make_float2(v0, v1);
                    s += v0 + v1; sq += v0 * v0 + v1 * v1;
                }
                s  += __shfl_xor_sync(0xffffffffu, s, 1);
                sq += __shfl_xor_sync(0xffffffffu, sq, 1);
                s  += __shfl_xor_sync(0xffffffffu, s, 2);
                sq += __shfl_xor_sync(0xffffffffu, sq, 2);
                if (tig == 0) {
                    atomicAdd(&red[2 * rloc],     s);
                    atomicAdd(&red[2 * rloc + 1], sq);
                }
            }
        }
        __syncthreads();
        #pragma unroll
        for (int mi = 0; mi < 4; mi++) {
            #pragma unroll
            for (int half = 0; half < 2; half++) {
                int rloc = warpM * 64 + mi * 16 + gid + half * 8;
                long orow = orows[mi][half];
                float mean = red[2 * rloc] * (1.0f / CDIM);
                float var  = red[2 * rloc + 1] * (1.0f / CDIM) - mean * mean;
                float rstd = rsqrtf(var + 1e-5f);
                #pragma unroll
                for (int ni = 0; ni < 4; ni++) {
                    int col = warpN * 32 + ni * 8 + 2 * tig;
                    float v0 = cc[mi][ni][half * 2 + 0];
                    float v1 = cc[mi][ni][half * 2 + 1];
                    float y0 = (v0 - mean) * rstd * gam[col]     + bet[col];
                    float y1 = (v1 - mean) * rstd * gam[col + 1] + bet[col + 1];
                    bf162 p = __float22bfloat162_rn(make_float2(y0, y1));
                    *(bf162*)(g_xw + orow * CDIM + col) = p;
                }
            }
        }
        return;
    }

    // epilogue (MODE 0/2/3)
    #pragma unroll
    for (int mi = 0; mi < 4; mi++) {
        #pragma unroll
        for (int half = 0; half < 2; half++) {
            long row = rowBase + warpM * 64 + mi * 16 + gid + half * 8;
            #pragma unroll
            for (int ni = 0; ni < 4; ni++) {
                int col = colBase + warpN * 32 + ni * 8 + 2 * tig;
                float v0 = cc[mi][ni][half * 2 + 0] + bias[col];
                float v1 = cc[mi][ni][half * 2 + 1] + bias[col + 1];
                if (MODE == 0) {
                    if (col < CDIM) { v0 *= 0.17677669529663687f; v1 *= 0.17677669529663687f; }
                }
                if (MODE == 2) {
                    v0 = 0.5f * v0 * (1.0f + erff(v0 * 0.70710678118654752f));
                    v1 = 0.5f * v1 * (1.0f + erff(v1 * 0.70710678118654752f));
                }
                if (MODE == 3) {
                    float* C = (float*)Cv;
                    const float2 r = *(const float2*)(resid + row * CDIM + col);
                    *(float2*)(C + row * CDIM + col) = make_float2(v0 + r.x, v1 + r.y);
                } else {
                    bf16* C = (bf16*)Cv;
                    bf162 p = __float22bfloat162_rn(make_float2(v0, v1));
                    *(bf162*)(C + row * (long)N + col) = p;
                }
            }
        }
    }
}

// ---------------------------------------------------------------------------
// BF16 tensor-core window attention (unchanged from round 4)
// ---------------------------------------------------------------------------
#define AQS 40
#define PSS 120
#define NPAD 112
__global__ __launch_bounds__(128)
void attn_kernel() {
    extern __shared__ bf16 asm_[];
    bf16* qs  = asm_;                          // [128][40]
    bf16* ks  = qs  + 128 * AQS;               // [112][40]
    bf16* vsr = ks  + NPAD * AQS;              // [112][40]
    bf16* ps  = vsr + NPAD * AQS;              // [128][120]

    const int w = blockIdx.x;
    const int h = blockIdx.y;
    const int tid  = threadIdx.x;
    const int warp = tid >> 5;
    const int lane = tid & 31;
    const int gid = lane >> 2;
    const int tig = lane & 3;

    const bf16* base = g_qkv + (size_t)w * NTOK * QKVN + h * HD;

    for (int i = tid; i < NTOK * 4; i += 128) {
        int m = i >> 2, c = (i & 3) * 8;
        *(uint4*)&qs [m * AQS + c] = *(const uint4*)(base + m * QKVN + c);
        *(uint4*)&ks [m * AQS + c] = *(const uint4*)(base + m * QKVN + CDIM + c);
        *(uint4*)&vsr[m * AQS + c] = *(const uint4*)(base + m * QKVN + 2 * CDIM + c);
    }
    const uint4 z4 = make_uint4(0, 0, 0, 0);
    for (int i = tid; i < 30 * 4; i += 128) {
        int m = 98 + (i >> 2), c = (i & 3) * 8;
        *(uint4*)&qs[m * AQS + c] = z4;
        if (m < NPAD) {
            *(uint4*)&ks [m * AQS + c] = z4;
            *(uint4*)&vsr[m * AQS + c] = z4;
        }
    }
    __syncthreads();

    const int a_r = (lane & 7) + ((lane >> 3) & 1) * 8;
    const int a_k = (lane >> 4) * 8;
    const int b_n = (lane & 7) + (lane >> 4) * 8;
    const int b_k = ((lane >> 3) & 1) * 8;
    const int t_r = (lane & 7) + ((lane >> 3) & 1) * 8;
    const int t_c = (lane >> 4) * 8;

    float cc[2][14][4];
    #pragma unroll
    for (int mi = 0; mi < 2; mi++)
        #pragma unroll
        for (int ni = 0; ni < 14; ni++)
            #pragma unroll
            for (int e = 0; e < 4; e++) cc[mi][ni][e] = 0.f;

    #pragma unroll
    for (int ksx = 0; ksx < 2; ksx++) {
        const int kk = ksx * 16;
        uint32_t af[2][4];
        #pragma unroll
        for (int mi = 0; mi < 2; mi++)
            ldsm_x4(af[mi], qs + (warp * 32 + mi * 16 + a_r) * AQS + kk + a_k);
        #pragma unroll
        for (int np = 0; np < 7; np++) {
            uint32_t r4[4];
            ldsm_x4(r4, ks + (np * 16 + b_n) * AQS + kk + b_k);
            uint32_t b0[2] = { r4[0], r4[1] };
            uint32_t b1[2] = { r4[2], r4[3] };
            mma_bf16(cc[0][2 * np],     af[0], b0);
            mma_bf16(cc[1][2 * np],     af[1], b0);
            mma_bf16(cc[0][2 * np + 1], af[0], b1);
            mma_bf16(cc[1][2 * np + 1], af[1], b1);
        }
    }

    float rsum[2][2] = {{0.f, 0.f}, {0.f, 0.f}};
    const float* gb = g_bias + h * NTOK * NTOK;
    #pragma unroll
    for (int mi = 0; mi < 2; mi++) {
        int r0 = warp * 32 + mi * 16 + gid;
        int r1 = r0 + 8;
        const float* b0p = gb + (r0 < NTOK ? r0 : NTOK - 1) * NTOK;
        const float* b1p = gb + (r1 < NTOK ? r1 : NTOK - 1) * NTOK;
        #pragma unroll
        for (int ni = 0; ni < 14; ni++) {
            int c0 = ni * 8 + 2 * tig;
            int c1 = c0 + 1;
            int cc0 = c0 < NTOK ? c0 : NTOK - 1;
            int cc1 = c1 < NTOK ? c1 : NTOK - 1;
            float e;
            e = (c0 < NTOK) ? __expf(cc[mi][ni][0] + b0p[cc0]) : 0.f; cc[mi][ni][0] = e; rsum[mi][0] += e;
            e = (c1 < NTOK) ? __expf(cc[mi][ni][1] + b0p[cc1]) : 0.f; cc[mi][ni][1] = e; rsum[mi][0] += e;
            e = (c0 < NTOK) ? __expf(cc[mi][ni][2] + b1p[cc0]) : 0.f; cc[mi][ni][2] = e; rsum[mi][1] += e;
            e = (c1 < NTOK) ? __expf(cc[mi][ni][3] + b1p[cc1]) : 0.f; cc[mi][ni][3] = e; rsum[mi][1] += e;
        }
    }
    float inv[2][2];
    #pragma unroll
    for (int mi = 0; mi < 2; mi++)
        #pragma unroll
        for (int hf = 0; hf < 2; hf++) {
            float s = rsum[mi][hf];
            s += __shfl_xor_sync(0xffffffffu, s, 1);
            s += __shfl_xor_sync(0xffffffffu, s, 2);
            inv[mi][hf] = 1.0f / s;
        }

    #pragma unroll
    for (int mi = 0; mi < 2; mi++) {
        int r0 = warp * 32 + mi * 16 + gid;
        #pragma unroll
        for (int ni = 0; ni < 14; ni++) {
            int col = ni * 8 + 2 * tig;
            bf162 p0 = __float22bfloat162_rn(
                make_float2(cc[mi][ni][0] * inv[mi][0], cc[mi][ni][1] * inv[mi][0]));
            bf162 p1 = __float22bfloat162_rn(
                make_float2(cc[mi][ni][2] * inv[mi][1], cc[mi][ni][3] * inv[mi][1]));
            *(bf162*)&ps[r0 * PSS + col]       = p0;
            *(bf162*)&ps[(r0 + 8) * PSS + col] = p1;
        }
    }
    __syncwarp();

    float oo[2][4][4];
    #pragma unroll
    for (int mi = 0; mi < 2; mi++)
        #pragma unroll
        for (int ni = 0; ni < 4; ni++)
            #pragma unroll
            for (int e = 0; e < 4; e++) oo[mi][ni][e] = 0.f;

    #pragma unroll
    for (int k2 = 0; k2 < 7; k2++) {
        const int kk = k2 * 16;
        uint32_t af[2][4];
        #pragma unroll
        for (int mi = 0; mi < 2; mi++)
            ldsm_x4(af[mi], ps + (warp * 32 + mi * 16 + a_r) * PSS + kk + a_k);
        #pragma unroll
        for (int np = 0; np < 2; np++) {
            int n0 = np * 16;
            uint32_t r4[4];
            ldsm_x4_t(r4, vsr + (kk + t_r) * AQS + n0 + t_c);
            uint32_t b0[2] = { r4[0], r4[1] };
            uint32_t b1[2] = { r4[2], r4[3] };
            mma_bf16(oo[0][2 * np],     af[0], b0);
            mma_bf16(oo[1][2 * np],     af[1], b0);
            mma_bf16(oo[0][2 * np + 1], af[0], b1);
            mma_bf16(oo[1][2 * np + 1], af[1], b1);
        }
    }

    #pragma unroll
    for (int mi = 0; mi < 2; mi++) {
        #pragma unroll
        for (int hf = 0; hf < 2; hf++) {
            int row = warp * 32 + mi * 16 + gid + hf * 8;
            if (row < NTOK) {
                bf16* op = g_attn + ((size_t)w * NTOK + row) * CDIM + h * HD;
                #pragma unroll
                for (int ni = 0; ni < 4; ni++) {
                    int col = ni * 8 + 2 * tig;
                    bf162 p = __float22bfloat162_rn(
                        make_float2(oo[mi][ni][hf * 2], oo[mi][ni][hf * 2 + 1]));
                    *(bf162*)(op + col) = p;
                }
            }
        }
    }
}

// ---------------------------------------------------------------------------
// launcher
// ---------------------------------------------------------------------------
extern "C" void kernel_launch(void* const* d_in, const int* in_sizes, int n_in,
                              void* d_out, int out_size) {
    const float* x          = (const float*)d_in[0];
    const float* norm1_w    = (const float*)d_in[1];
    const float* norm1_b    = (const float*)d_in[2];
    const float* qkv_w      = (const float*)d_in[3];
    const float* qkv_b      = (const float*)d_in[4];
    const float* bias_table = (const float*)d_in[5];
    const float* proj_w     = (const float*)d_in[6];
    const float* proj_b     = (const float*)d_in[7];
    const float* norm2_w    = (const float*)d_in[8];
    const float* norm2_b    = (const float*)d_in[9];
    const float* fc1_w      = (const float*)d_in[10];
    const float* fc1_b      = (const float*)d_in[11];
    const float* fc2_w      = (const float*)d_in[12];
    const float* fc2_b      = (const float*)d_in[13];
    const int*   rel_index  = (const int*)d_in[14];
    float* out = (float*)d_out;

    bf16 *p_xw, *p_qkv, *p_attn, *p_h;
    bf16 *p_wq, *p_wp, *p_w1, *p_w2;
    float *p_x2;
    cudaGetSymbolAddress((void**)&p_xw,   g_xw);
    cudaGetSymbolAddress((void**)&p_qkv,  g_qkv);
    cudaGetSymbolAddress((void**)&p_attn, g_attn);
    cudaGetSymbolAddress((void**)&p_x2,   g_x2);
    cudaGetSymbolAddress((void**)&p_h,    g_h);
    cudaGetSymbolAddress((void**)&p_wq,   g_wq);
    cudaGetSymbolAddress((void**)&p_wp,   g_wp);
    cudaGetSymbolAddress((void**)&p_w1,   g_w1);
    cudaGetSymbolAddress((void**)&p_w2,   g_w2);

    const int GEMM_SMEM = 3 * G_STAGE * (int)sizeof(bf16);   // 61440
    const int ATTN_SMEM = (128 * AQS + 2 * NPAD * AQS + 128 * PSS) * (int)sizeof(bf16);
    cudaFuncSetAttribute((const void*)gemm_kernel<0,128>, cudaFuncAttributeMaxDynamicSharedMemorySize, GEMM_SMEM);
    cudaFuncSetAttribute((const void*)gemm_kernel<1,128>, cudaFuncAttributeMaxDynamicSharedMemorySize, GEMM_SMEM);
    cudaFuncSetAttribute((const void*)gemm_kernel<2,128>, cudaFuncAttributeMaxDynamicSharedMemorySize, GEMM_SMEM);
    cudaFuncSetAttribute((const void*)gemm_kernel<3,512>, cudaFuncAttributeMaxDynamicSharedMemorySize, GEMM_SMEM);
    cudaFuncSetAttribute((const void*)attn_kernel,        cudaFuncAttributeMaxDynamicSharedMemorySize, ATTN_SMEM);

    // 0) weight conversion + bias gather
    cvt_weights_kernel<<<49152 / 256, 256>>>(qkv_w, proj_w, fc1_w, fc2_w);
    bias_gather_kernel<<<dim3(NTOK, NH), NTOK>>>(bias_table, rel_index);

    // 1) LN1 + window partition (fp32 -> bf16)
    ln_kernel<true><<<TOK / 8, 256>>>(x, norm1_w, norm1_b, p_xw);

    // 2) QKV gemm (+ q scale), bf16 out
    gemm_kernel<0,128><<<dim3(QKVN / 128, TOK / 128), 256, GEMM_SMEM>>>(
        p_xw, p_wq, qkv_b, nullptr, nullptr, nullptr, p_qkv, QKVN);

    // 3) window attention (bf16 tensor cores)
    attn_kernel<<<dim3(NWIN, NH), 128, ATTN_SMEM>>>();

    // 4) proj gemm + window reverse + residual(x) -> g_x2 (fp32)  + fused LN2 -> g_xw (bf16)
    gemm_kernel<1,128><<<dim3(CDIM / 128, TOK / 128), 256, GEMM_SMEM>>>(
        p_attn, p_wp, proj_b, x, norm2_w, norm2_b, p_x2, CDIM);

    // 5) fc1 + exact GELU, bf16 out
    gemm_kernel<2,128><<<dim3(CH / 128, TOK / 128), 256, GEMM_SMEM>>>(
        p_xw, p_w1, fc1_b, nullptr, nullptr, nullptr, p_h, CH);

    // 6) fc2 + residual(g_x2) -> d_out (fp32)
    gemm_kernel<3,512><<<dim3(CDIM / 128, TOK / 128), 256, GEMM_SMEM>>>(
        p_h, p_w2, fc2_b, p_x2, nullptr, nullptr, out, CDIM);

    (void)in_sizes; (void)n_in; (void)out_size;
}